// round 3
// baseline (speedup 1.0000x reference)
#include <cuda_runtime.h>
#include <cuda_bf16.h>
#include <math.h>

#define N_NODES 50000
#define N_EDGES 625000
#define DIM 128
#define N_LAYERS 3
#define N_GRAPHS 64
#define LN_EPS 1e-5f

// ---------------- device scratch ----------------
__device__ float g_h[N_NODES * DIM];
__device__ float g_z[N_NODES * DIM];
__device__ float g_aF[N_NODES * DIM];
__device__ float g_aB[N_NODES * DIM];
__device__ float g_scores[N_NODES];
__device__ float g_M[9 * DIM * DIM];   // [layer][mat 0..2][128][128]
__device__ float g_bc[N_LAYERS * DIM]; // fused bias per layer
__device__ int   g_is64;               // 1 if index buffers are int64, 0 if int32

// ---------------- dtype detection ----------------
__global__ void detect_kernel(const unsigned int* __restrict__ p)
{
    __shared__ int nz;
    if (threadIdx.x == 0) nz = 0;
    __syncthreads();
    for (int i = threadIdx.x; i < 4096; i += blockDim.x)
        if (p[2 * i + 1] != 0u) atomicOr(&nz, 1);
    __syncthreads();
    if (threadIdx.x == 0) g_is64 = nz ? 0 : 1;
}

__device__ __forceinline__ int load_idx(const void* buf, long long i)
{
    int v;
    if (g_is64) v = (int)((const long long*)buf)[i];
    else        v = ((const int*)buf)[i];
    v = v < 0 ? 0 : (v >= N_NODES ? N_NODES - 1 : v);
    return v;
}

// ---------------- prep: M_m = Wcomb_chunk_m @ W_m  ----------------
__global__ void prep_M_kernel(const float* __restrict__ Wcomb,
                              const float* __restrict__ Wself,
                              const float* __restrict__ Wfwd,
                              const float* __restrict__ Wbwd,
                              float* __restrict__ M)
{
    int b = blockIdx.x;
    int rc = b & 7;
    int m  = (b >> 3) % 3;
    int l  = b / 24;
    const float* src = (m == 0) ? (Wself + l * DIM * DIM)
                   : (m == 1) ? (Wfwd + l * DIM * DIM)
                              : (Wbwd + l * DIM * DIM);
    int j = threadIdx.x;

    __shared__ float wcs[16][DIM];
    #pragma unroll
    for (int i = 0; i < 16; i++) {
        int row = rc * 16 + i;
        wcs[i][j] = Wcomb[l * DIM * 3 * DIM + row * 3 * DIM + m * DIM + j];
    }
    __syncthreads();

    float acc[16];
    #pragma unroll
    for (int i = 0; i < 16; i++) acc[i] = 0.0f;

    for (int k = 0; k < DIM; k++) {
        float w = src[k * DIM + j];
        #pragma unroll
        for (int i = 0; i < 16; i++) acc[i] += wcs[i][k] * w;
    }
    float* dst = M + (l * 3 + m) * DIM * DIM;
    #pragma unroll
    for (int i = 0; i < 16; i++) dst[(rc * 16 + i) * DIM + j] = acc[i];
}

__global__ void prep_b_kernel(const float* __restrict__ Wcomb,
                              const float* __restrict__ bself,
                              const float* __restrict__ bcomb,
                              float* __restrict__ bc)
{
    int l = blockIdx.x;
    int i = threadIdx.x;
    float s = bcomb[l * DIM + i];
    for (int k = 0; k < DIM; k++)
        s += Wcomb[l * DIM * 3 * DIM + i * 3 * DIM + k] * bself[l * DIM + k];
    bc[l * DIM + i] = s;
}

// ---------------- tiled GEMM: out[n,j] = sum_s sum_k A_s[n,k] * W_s[j,k] (+bias)(relu) ----
#define GSMEM_FLOATS (128 * 65 + 128 * 129)

__global__ void gemm3_kernel(const float* __restrict__ A0, const float* __restrict__ W0,
                             const float* __restrict__ A1, const float* __restrict__ W1,
                             const float* __restrict__ A2, const float* __restrict__ W2,
                             const float* __restrict__ bias,
                             float* __restrict__ out,
                             int n, int relu)
{
    extern __shared__ float sm[];
    float* hs = sm;              // stride 65
    float* ws = sm + 128 * 65;   // stride 129

    int tid = threadIdx.x;
    int tx = tid & 15;       // col group: cols tx + 16*c
    int ty = tid >> 4;       // row group: rows ty*4 + r
    int base = blockIdx.x * 64;
    int ty4 = ty * 4;

    float acc[4][8];
    #pragma unroll
    for (int r = 0; r < 4; r++)
        #pragma unroll
        for (int c = 0; c < 8; c++) acc[r][c] = 0.0f;

    #pragma unroll
    for (int s = 0; s < 3; s++) {
        const float* A = (s == 0) ? A0 : (s == 1) ? A1 : A2;
        const float* W = (s == 0) ? W0 : (s == 1) ? W1 : W2;
        if (A == nullptr) continue;

        __syncthreads();
        // node tile: 64 x 128 = 2048 float4 -> 8 iters
        #pragma unroll
        for (int it = 0; it < 8; it++) {
            int i = tid + it * 256;       // 0..2047
            int nloc = i >> 5;            // 0..63
            int k4 = i & 31;              // 0..31
            int gn = base + nloc;
            float4 v = make_float4(0.f, 0.f, 0.f, 0.f);
            if (gn < n)
                v = *reinterpret_cast<const float4*>(A + (size_t)gn * DIM + k4 * 4);
            hs[(k4 * 4 + 0) * 65 + nloc] = v.x;
            hs[(k4 * 4 + 1) * 65 + nloc] = v.y;
            hs[(k4 * 4 + 2) * 65 + nloc] = v.z;
            hs[(k4 * 4 + 3) * 65 + nloc] = v.w;
        }
        // W tile: 128 x 128 = 4096 float4 -> 16 iters (FIXED: was 8, left j>=64 garbage)
        #pragma unroll
        for (int it = 0; it < 16; it++) {
            int i = tid + it * 256;       // 0..4095
            int j = i >> 5;               // 0..127
            int k4 = i & 31;              // 0..31
            float4 v = *reinterpret_cast<const float4*>(W + (size_t)j * DIM + k4 * 4);
            ws[(k4 * 4 + 0) * 129 + j] = v.x;
            ws[(k4 * 4 + 1) * 129 + j] = v.y;
            ws[(k4 * 4 + 2) * 129 + j] = v.z;
            ws[(k4 * 4 + 3) * 129 + j] = v.w;
        }
        __syncthreads();

        const float* hp = hs + ty4;
        const float* wp = ws + tx;
        #pragma unroll 4
        for (int k = 0; k < 128; k++) {
            float a0 = hp[k * 65 + 0];
            float a1 = hp[k * 65 + 1];
            float a2 = hp[k * 65 + 2];
            float a3 = hp[k * 65 + 3];
            #pragma unroll
            for (int c = 0; c < 8; c++) {
                float w = wp[k * 129 + 16 * c];
                acc[0][c] += a0 * w;
                acc[1][c] += a1 * w;
                acc[2][c] += a2 * w;
                acc[3][c] += a3 * w;
            }
        }
    }

    #pragma unroll
    for (int r = 0; r < 4; r++) {
        int gn = base + ty4 + r;
        if (gn >= n) continue;
        #pragma unroll
        for (int c = 0; c < 8; c++) {
            int j = tx + 16 * c;
            float v = acc[r][c];
            if (bias) v += bias[j];
            if (relu) v = fmaxf(v, 0.0f);
            out[(size_t)gn * DIM + j] = v;
        }
    }
}

// ---------------- scores ----------------
__global__ void scores_kernel(const float* __restrict__ h,
                              const float* __restrict__ wsc,
                              const float* __restrict__ bsc,
                              float* __restrict__ scores, int n)
{
    int wid = (blockIdx.x * blockDim.x + threadIdx.x) >> 5;
    int lane = threadIdx.x & 31;
    if (wid >= n) return;
    float4 hv = reinterpret_cast<const float4*>(h + (size_t)wid * DIM)[lane];
    float4 wv = reinterpret_cast<const float4*>(wsc)[lane];
    float p = hv.x * wv.x + hv.y * wv.y + hv.z * wv.z + hv.w * wv.w;
    #pragma unroll
    for (int o = 16; o > 0; o >>= 1) p += __shfl_xor_sync(0xFFFFFFFFu, p, o);
    if (lane == 0) scores[wid] = p + bsc[0];
}

// ---------------- zero ----------------
__global__ void zero_kernel(float4* __restrict__ p, int n4)
{
    int i = blockIdx.x * blockDim.x + threadIdx.x;
    if (i < n4) p[i] = make_float4(0.f, 0.f, 0.f, 0.f);
}

// ---------------- edge scatter: warp per edge ----------------
__global__ void edge_kernel(const void* __restrict__ ei,
                            const float* __restrict__ scores,
                            const float* __restrict__ h,
                            float* __restrict__ aF,
                            float* __restrict__ aB)
{
    int wid = (blockIdx.x * blockDim.x + threadIdx.x) >> 5;
    int lane = threadIdx.x & 31;
    if (wid >= N_EDGES) return;
    int s = load_idx(ei, wid);
    int d = load_idx(ei, (long long)N_EDGES + wid);
    float diff = scores[s] - scores[d];
    float a = 1.0f / (1.0f + expf(-diff));
    float b = 1.0f - a;
    float4 v = reinterpret_cast<const float4*>(h + (size_t)s * DIM)[lane];
    float* pf = aF + (size_t)d * DIM + lane * 4;
    float* pb = aB + (size_t)d * DIM + lane * 4;
    asm volatile("red.global.add.v4.f32 [%0], {%1,%2,%3,%4};"
                 :: "l"(pf), "f"(v.x * a), "f"(v.y * a), "f"(v.z * a), "f"(v.w * a)
                 : "memory");
    asm volatile("red.global.add.v4.f32 [%0], {%1,%2,%3,%4};"
                 :: "l"(pb), "f"(v.x * b), "f"(v.y * b), "f"(v.z * b), "f"(v.w * b)
                 : "memory");
}

// ---------------- LayerNorm + relu + residual ----------------
__global__ void ln_kernel(const float* __restrict__ z,
                          const float* __restrict__ gamma,
                          const float* __restrict__ beta,
                          float* __restrict__ h, int n)
{
    int wid = (blockIdx.x * blockDim.x + threadIdx.x) >> 5;
    int lane = threadIdx.x & 31;
    if (wid >= n) return;
    float4 zv = reinterpret_cast<const float4*>(z + (size_t)wid * DIM)[lane];
    float s = zv.x + zv.y + zv.z + zv.w;
    #pragma unroll
    for (int o = 16; o > 0; o >>= 1) s += __shfl_xor_sync(0xFFFFFFFFu, s, o);
    float mu = s * (1.0f / 128.0f);
    float dx = zv.x - mu, dy = zv.y - mu, dz = zv.z - mu, dw = zv.w - mu;
    float q = dx * dx + dy * dy + dz * dz + dw * dw;
    #pragma unroll
    for (int o = 16; o > 0; o >>= 1) q += __shfl_xor_sync(0xFFFFFFFFu, q, o);
    float rs = rsqrtf(q * (1.0f / 128.0f) + LN_EPS);
    float4 g = reinterpret_cast<const float4*>(gamma)[lane];
    float4 b = reinterpret_cast<const float4*>(beta)[lane];
    float4* hp = reinterpret_cast<float4*>(h + (size_t)wid * DIM);
    float4 hv = hp[lane];
    float4 r;
    r.x = fmaxf(dx * rs * g.x + b.x, 0.0f) + hv.x;
    r.y = fmaxf(dy * rs * g.y + b.y, 0.0f) + hv.y;
    r.z = fmaxf(dz * rs * g.z + b.z, 0.0f) + hv.z;
    r.w = fmaxf(dw * rs * g.w + b.w, 0.0f) + hv.w;
    hp[lane] = r;
}

// ---------------- pool ----------------
__device__ __forceinline__ int lb_idx(const void* buf, int n, int val)
{
    int lo = 0, hi = n;
    while (lo < hi) {
        int mid = (lo + hi) >> 1;
        int bv;
        if (g_is64) bv = (int)((const long long*)buf)[mid];
        else        bv = ((const int*)buf)[mid];
        if (bv < val) lo = mid + 1; else hi = mid;
    }
    return lo;
}

__global__ void pool_kernel(const float* __restrict__ h,
                            const void* __restrict__ batch,
                            float* __restrict__ out)
{
    int g = blockIdx.x;
    int j = threadIdx.x;
    __shared__ int s_lo, s_hi;
    if (j == 0) {
        s_lo = lb_idx(batch, N_NODES, g);
        s_hi = lb_idx(batch, N_NODES, g + 1);
    }
    __syncthreads();
    float sum = 0.0f;
    for (int nd = s_lo; nd < s_hi; nd++) sum += h[(size_t)nd * DIM + j];
    float c = (float)(s_hi - s_lo);
    out[g * DIM + j] = sum / fmaxf(c, 1.0f);
}

// ---------------- launch ----------------
extern "C" void kernel_launch(void* const* d_in, const int* in_sizes, int n_in,
                              void* d_out, int out_size)
{
    const float* x      = (const float*)d_in[0];
    const void*  ei     = d_in[1];
    const void*  batch  = d_in[2];
    const float* Wemb   = (const float*)d_in[3];
    const float* bemb   = (const float*)d_in[4];
    const float* Wscore = (const float*)d_in[5];
    const float* bscore = (const float*)d_in[6];
    const float* Wfwd   = (const float*)d_in[7];
    const float* Wbwd   = (const float*)d_in[8];
    const float* Wself  = (const float*)d_in[9];
    const float* bself  = (const float*)d_in[10];
    const float* Wcomb  = (const float*)d_in[11];
    const float* bcomb  = (const float*)d_in[12];
    const float* gamma  = (const float*)d_in[13];
    const float* beta   = (const float*)d_in[14];
    float* out = (float*)d_out;

    float *pH, *pZ, *pAF, *pAB, *pS, *pM, *pBC;
    cudaGetSymbolAddress((void**)&pH,  g_h);
    cudaGetSymbolAddress((void**)&pZ,  g_z);
    cudaGetSymbolAddress((void**)&pAF, g_aF);
    cudaGetSymbolAddress((void**)&pAB, g_aB);
    cudaGetSymbolAddress((void**)&pS,  g_scores);
    cudaGetSymbolAddress((void**)&pM,  g_M);
    cudaGetSymbolAddress((void**)&pBC, g_bc);

    const int smemBytes = GSMEM_FLOATS * sizeof(float);
    cudaFuncSetAttribute(gemm3_kernel, cudaFuncAttributeMaxDynamicSharedMemorySize, smemBytes);

    const int gemmBlocks = (N_NODES + 63) / 64;     // 782
    const int warpBlocks = (N_NODES + 7) / 8;       // 6250
    const int edgeBlocks = (N_EDGES + 7) / 8;       // 78125
    const int zeroN4 = N_NODES * DIM / 4;
    const int zeroBlocks = (zeroN4 + 255) / 256;

    detect_kernel<<<1, 256>>>((const unsigned int*)ei);

    prep_M_kernel<<<72, 128>>>(Wcomb, Wself, Wfwd, Wbwd, pM);
    prep_b_kernel<<<N_LAYERS, 128>>>(Wcomb, bself, bcomb, pBC);

    // embed: h = relu(x @ Wemb^T + bemb)
    gemm3_kernel<<<gemmBlocks, 256, smemBytes>>>(x, Wemb, nullptr, nullptr, nullptr, nullptr,
                                                 bemb, pH, N_NODES, 1);

    for (int l = 0; l < N_LAYERS; l++) {
        scores_kernel<<<warpBlocks, 256>>>(pH, Wscore + l * DIM, bscore + l, pS, N_NODES);
        zero_kernel<<<zeroBlocks, 256>>>((float4*)pAF, zeroN4);
        zero_kernel<<<zeroBlocks, 256>>>((float4*)pAB, zeroN4);
        edge_kernel<<<edgeBlocks, 256>>>(ei, pS, pH, pAF, pAB);
        gemm3_kernel<<<gemmBlocks, 256, smemBytes>>>(
            pH,  pM + (l * 3 + 0) * DIM * DIM,
            pAF, pM + (l * 3 + 1) * DIM * DIM,
            pAB, pM + (l * 3 + 2) * DIM * DIM,
            pBC + l * DIM, pZ, N_NODES, 0);
        ln_kernel<<<warpBlocks, 256>>>(pZ, gamma + l * DIM, beta + l * DIM, pH, N_NODES);
    }

    pool_kernel<<<N_GRAPHS, DIM>>>(pH, batch, out);
}

// round 4
// speedup vs baseline: 1.1376x; 1.1376x over previous
#include <cuda_runtime.h>
#include <cuda_bf16.h>
#include <math.h>

#define N_NODES 50000
#define N_EDGES 625000
#define DIM 128
#define N_LAYERS 3
#define N_GRAPHS 64
#define LN_EPS 1e-5f

// ---------------- device scratch ----------------
__device__ float g_h[N_NODES * DIM];
__device__ float g_z[N_NODES * DIM];
__device__ float g_aF[N_NODES * DIM];
__device__ float g_aB[N_NODES * DIM];
__device__ float g_scores[N_NODES];
__device__ float g_M[9 * DIM * DIM];
__device__ float g_bc[N_LAYERS * DIM];
__device__ int   g_is64;
// CSR scratch
__device__ int g_deg[N_NODES];
__device__ int g_off[N_NODES + 1];
__device__ int g_cur[N_NODES];
__device__ int g_srcE[N_EDGES];
__device__ int g_dstE[N_EDGES];
__device__ int g_srcS[N_EDGES];   // src indices sorted by dst

// ---------------- dtype detection ----------------
__global__ void detect_kernel(const unsigned int* __restrict__ p)
{
    __shared__ int nz;
    if (threadIdx.x == 0) nz = 0;
    __syncthreads();
    for (int i = threadIdx.x; i < 4096; i += blockDim.x)
        if (p[2 * i + 1] != 0u) atomicOr(&nz, 1);
    __syncthreads();
    if (threadIdx.x == 0) g_is64 = nz ? 0 : 1;
}

__device__ __forceinline__ int load_idx(const void* buf, long long i)
{
    int v;
    if (g_is64) v = (int)((const long long*)buf)[i];
    else        v = ((const int*)buf)[i];
    v = v < 0 ? 0 : (v >= N_NODES ? N_NODES - 1 : v);
    return v;
}

// ---------------- CSR build ----------------
__global__ void zero_int_kernel(int* __restrict__ p, int n)
{
    int i = blockIdx.x * blockDim.x + threadIdx.x;
    if (i < n) p[i] = 0;
}

__global__ void count_kernel(const void* __restrict__ ei,
                             int* __restrict__ deg,
                             int* __restrict__ srcE,
                             int* __restrict__ dstE)
{
    int e = blockIdx.x * blockDim.x + threadIdx.x;
    if (e >= N_EDGES) return;
    int s = load_idx(ei, e);
    int d = load_idx(ei, (long long)N_EDGES + e);
    srcE[e] = s;
    dstE[e] = d;
    atomicAdd(&deg[d], 1);
}

// single block, 1024 threads: exclusive scan of deg -> off (and cur copy)
__global__ void scan_kernel(const int* __restrict__ deg,
                            int* __restrict__ off,
                            int* __restrict__ cur)
{
    __shared__ int part[1024];
    int t = threadIdx.x;
    const int CH = (N_NODES + 1023) / 1024;   // 49
    int start = t * CH;
    int s = 0;
    for (int i = 0; i < CH; i++) {
        int idx = start + i;
        if (idx < N_NODES) s += deg[idx];
    }
    part[t] = s;
    __syncthreads();
    for (int o = 1; o < 1024; o <<= 1) {
        int v = 0;
        if (t >= o) v = part[t - o];
        __syncthreads();
        if (t >= o) part[t] += v;
        __syncthreads();
    }
    int run = (t == 0) ? 0 : part[t - 1];
    for (int i = 0; i < CH; i++) {
        int idx = start + i;
        if (idx < N_NODES) {
            off[idx] = run;
            cur[idx] = run;
            run += deg[idx];
        }
    }
    if (t == 1023) off[N_NODES] = run;
}

__global__ void scatter_kernel(const int* __restrict__ srcE,
                               const int* __restrict__ dstE,
                               int* __restrict__ cur,
                               int* __restrict__ srcS)
{
    int e = blockIdx.x * blockDim.x + threadIdx.x;
    if (e >= N_EDGES) return;
    int pos = atomicAdd(&cur[dstE[e]], 1);
    srcS[pos] = srcE[e];
}

// ---------------- aggregation: warp per destination node, no atomics ----------------
__global__ void agg_kernel(const int* __restrict__ off,
                           const int* __restrict__ srcS,
                           const float* __restrict__ scores,
                           const float* __restrict__ h,
                           float* __restrict__ aF,
                           float* __restrict__ aB)
{
    int node = (blockIdx.x * blockDim.x + threadIdx.x) >> 5;
    int lane = threadIdx.x & 31;
    if (node >= N_NODES) return;
    int lo = off[node], hi = off[node + 1];
    float sd = scores[node];
    float4 af = make_float4(0.f, 0.f, 0.f, 0.f);
    float4 ab = make_float4(0.f, 0.f, 0.f, 0.f);
    for (int e = lo; e < hi; e++) {
        int s = srcS[e];
        float a = 1.0f / (1.0f + expf(sd - scores[s]));   // sigmoid(ss - sd)
        float b = 1.0f - a;
        float4 v = reinterpret_cast<const float4*>(h + (size_t)s * DIM)[lane];
        af.x += v.x * a; af.y += v.y * a; af.z += v.z * a; af.w += v.w * a;
        ab.x += v.x * b; ab.y += v.y * b; ab.z += v.z * b; ab.w += v.w * b;
    }
    reinterpret_cast<float4*>(aF + (size_t)node * DIM)[lane] = af;
    reinterpret_cast<float4*>(aB + (size_t)node * DIM)[lane] = ab;
}

// ---------------- prep: M_m = Wcomb_chunk_m @ W_m ----------------
__global__ void prep_M_kernel(const float* __restrict__ Wcomb,
                              const float* __restrict__ Wself,
                              const float* __restrict__ Wfwd,
                              const float* __restrict__ Wbwd,
                              float* __restrict__ M)
{
    int b = blockIdx.x;
    int rc = b & 7;
    int m  = (b >> 3) % 3;
    int l  = b / 24;
    const float* src = (m == 0) ? (Wself + l * DIM * DIM)
                   : (m == 1) ? (Wfwd + l * DIM * DIM)
                              : (Wbwd + l * DIM * DIM);
    int j = threadIdx.x;

    __shared__ float wcs[16][DIM];
    #pragma unroll
    for (int i = 0; i < 16; i++) {
        int row = rc * 16 + i;
        wcs[i][j] = Wcomb[l * DIM * 3 * DIM + row * 3 * DIM + m * DIM + j];
    }
    __syncthreads();

    float acc[16];
    #pragma unroll
    for (int i = 0; i < 16; i++) acc[i] = 0.0f;

    for (int k = 0; k < DIM; k++) {
        float w = src[k * DIM + j];
        #pragma unroll
        for (int i = 0; i < 16; i++) acc[i] += wcs[i][k] * w;
    }
    float* dst = M + (l * 3 + m) * DIM * DIM;
    #pragma unroll
    for (int i = 0; i < 16; i++) dst[(rc * 16 + i) * DIM + j] = acc[i];
}

__global__ void prep_b_kernel(const float* __restrict__ Wcomb,
                              const float* __restrict__ bself,
                              const float* __restrict__ bcomb,
                              float* __restrict__ bc)
{
    int l = blockIdx.x;
    int i = threadIdx.x;
    float s = bcomb[l * DIM + i];
    for (int k = 0; k < DIM; k++)
        s += Wcomb[l * DIM * 3 * DIM + i * 3 * DIM + k] * bself[l * DIM + k];
    bc[l * DIM + i] = s;
}

// ---------------- tiled GEMM (unchanged, known-good) ----------------
#define GSMEM_FLOATS (128 * 65 + 128 * 129)

__global__ void gemm3_kernel(const float* __restrict__ A0, const float* __restrict__ W0,
                             const float* __restrict__ A1, const float* __restrict__ W1,
                             const float* __restrict__ A2, const float* __restrict__ W2,
                             const float* __restrict__ bias,
                             float* __restrict__ out,
                             int n, int relu)
{
    extern __shared__ float sm[];
    float* hs = sm;              // stride 65
    float* ws = sm + 128 * 65;   // stride 129

    int tid = threadIdx.x;
    int tx = tid & 15;
    int ty = tid >> 4;
    int base = blockIdx.x * 64;
    int ty4 = ty * 4;

    float acc[4][8];
    #pragma unroll
    for (int r = 0; r < 4; r++)
        #pragma unroll
        for (int c = 0; c < 8; c++) acc[r][c] = 0.0f;

    #pragma unroll
    for (int s = 0; s < 3; s++) {
        const float* A = (s == 0) ? A0 : (s == 1) ? A1 : A2;
        const float* W = (s == 0) ? W0 : (s == 1) ? W1 : W2;
        if (A == nullptr) continue;

        __syncthreads();
        #pragma unroll
        for (int it = 0; it < 8; it++) {
            int i = tid + it * 256;
            int nloc = i >> 5;
            int k4 = i & 31;
            int gn = base + nloc;
            float4 v = make_float4(0.f, 0.f, 0.f, 0.f);
            if (gn < n)
                v = *reinterpret_cast<const float4*>(A + (size_t)gn * DIM + k4 * 4);
            hs[(k4 * 4 + 0) * 65 + nloc] = v.x;
            hs[(k4 * 4 + 1) * 65 + nloc] = v.y;
            hs[(k4 * 4 + 2) * 65 + nloc] = v.z;
            hs[(k4 * 4 + 3) * 65 + nloc] = v.w;
        }
        #pragma unroll
        for (int it = 0; it < 16; it++) {
            int i = tid + it * 256;
            int j = i >> 5;
            int k4 = i & 31;
            float4 v = *reinterpret_cast<const float4*>(W + (size_t)j * DIM + k4 * 4);
            ws[(k4 * 4 + 0) * 129 + j] = v.x;
            ws[(k4 * 4 + 1) * 129 + j] = v.y;
            ws[(k4 * 4 + 2) * 129 + j] = v.z;
            ws[(k4 * 4 + 3) * 129 + j] = v.w;
        }
        __syncthreads();

        const float* hp = hs + ty4;
        const float* wp = ws + tx;
        #pragma unroll 4
        for (int k = 0; k < 128; k++) {
            float a0 = hp[k * 65 + 0];
            float a1 = hp[k * 65 + 1];
            float a2 = hp[k * 65 + 2];
            float a3 = hp[k * 65 + 3];
            #pragma unroll
            for (int c = 0; c < 8; c++) {
                float w = wp[k * 129 + 16 * c];
                acc[0][c] += a0 * w;
                acc[1][c] += a1 * w;
                acc[2][c] += a2 * w;
                acc[3][c] += a3 * w;
            }
        }
    }

    #pragma unroll
    for (int r = 0; r < 4; r++) {
        int gn = base + ty4 + r;
        if (gn >= n) continue;
        #pragma unroll
        for (int c = 0; c < 8; c++) {
            int j = tx + 16 * c;
            float v = acc[r][c];
            if (bias) v += bias[j];
            if (relu) v = fmaxf(v, 0.0f);
            out[(size_t)gn * DIM + j] = v;
        }
    }
}

// ---------------- scores (layer 0 only) ----------------
__global__ void scores_kernel(const float* __restrict__ h,
                              const float* __restrict__ wsc,
                              const float* __restrict__ bsc,
                              float* __restrict__ scores, int n)
{
    int wid = (blockIdx.x * blockDim.x + threadIdx.x) >> 5;
    int lane = threadIdx.x & 31;
    if (wid >= n) return;
    float4 hv = reinterpret_cast<const float4*>(h + (size_t)wid * DIM)[lane];
    float4 wv = reinterpret_cast<const float4*>(wsc)[lane];
    float p = hv.x * wv.x + hv.y * wv.y + hv.z * wv.z + hv.w * wv.w;
    #pragma unroll
    for (int o = 16; o > 0; o >>= 1) p += __shfl_xor_sync(0xFFFFFFFFu, p, o);
    if (lane == 0) scores[wid] = p + bsc[0];
}

// ---------------- LayerNorm + relu + residual (+ fused next-layer scores) ----------------
__global__ void ln_kernel(const float* __restrict__ z,
                          const float* __restrict__ gamma,
                          const float* __restrict__ beta,
                          float* __restrict__ h, int n,
                          const float* __restrict__ wsc,
                          const float* __restrict__ bsc,
                          float* __restrict__ scoresOut)
{
    int wid = (blockIdx.x * blockDim.x + threadIdx.x) >> 5;
    int lane = threadIdx.x & 31;
    if (wid >= n) return;
    float4 zv = reinterpret_cast<const float4*>(z + (size_t)wid * DIM)[lane];
    float s = zv.x + zv.y + zv.z + zv.w;
    #pragma unroll
    for (int o = 16; o > 0; o >>= 1) s += __shfl_xor_sync(0xFFFFFFFFu, s, o);
    float mu = s * (1.0f / 128.0f);
    float dx = zv.x - mu, dy = zv.y - mu, dz = zv.z - mu, dw = zv.w - mu;
    float q = dx * dx + dy * dy + dz * dz + dw * dw;
    #pragma unroll
    for (int o = 16; o > 0; o >>= 1) q += __shfl_xor_sync(0xFFFFFFFFu, q, o);
    float rs = rsqrtf(q * (1.0f / 128.0f) + LN_EPS);
    float4 g = reinterpret_cast<const float4*>(gamma)[lane];
    float4 b = reinterpret_cast<const float4*>(beta)[lane];
    float4* hp = reinterpret_cast<float4*>(h + (size_t)wid * DIM);
    float4 hv = hp[lane];
    float4 r;
    r.x = fmaxf(dx * rs * g.x + b.x, 0.0f) + hv.x;
    r.y = fmaxf(dy * rs * g.y + b.y, 0.0f) + hv.y;
    r.z = fmaxf(dz * rs * g.z + b.z, 0.0f) + hv.z;
    r.w = fmaxf(dw * rs * g.w + b.w, 0.0f) + hv.w;
    hp[lane] = r;

    if (wsc) {
        float4 wv = reinterpret_cast<const float4*>(wsc)[lane];
        float p = r.x * wv.x + r.y * wv.y + r.z * wv.z + r.w * wv.w;
        #pragma unroll
        for (int o = 16; o > 0; o >>= 1) p += __shfl_xor_sync(0xFFFFFFFFu, p, o);
        if (lane == 0) scoresOut[wid] = p + bsc[0];
    }
}

// ---------------- pool ----------------
__device__ __forceinline__ int lb_idx(const void* buf, int n, int val)
{
    int lo = 0, hi = n;
    while (lo < hi) {
        int mid = (lo + hi) >> 1;
        int bv;
        if (g_is64) bv = (int)((const long long*)buf)[mid];
        else        bv = ((const int*)buf)[mid];
        if (bv < val) lo = mid + 1; else hi = mid;
    }
    return lo;
}

__global__ void zero_out_kernel(float* __restrict__ p, int n)
{
    int i = blockIdx.x * blockDim.x + threadIdx.x;
    if (i < n) p[i] = 0.0f;
}

// grid (64, 8): block (g, slice) sums rows lo+slice, lo+slice+8, ...
__global__ void pool_kernel(const float* __restrict__ h,
                            const void* __restrict__ batch,
                            float* __restrict__ out)
{
    int g = blockIdx.x;
    int slice = blockIdx.y;
    int j = threadIdx.x;
    __shared__ int s_lo, s_hi;
    if (j == 0) {
        s_lo = lb_idx(batch, N_NODES, g);
        s_hi = lb_idx(batch, N_NODES, g + 1);
    }
    __syncthreads();
    float sum = 0.0f;
    for (int nd = s_lo + slice; nd < s_hi; nd += 8)
        sum += h[(size_t)nd * DIM + j];
    float c = fmaxf((float)(s_hi - s_lo), 1.0f);
    atomicAdd(&out[g * DIM + j], sum / c);
}

// ---------------- launch ----------------
extern "C" void kernel_launch(void* const* d_in, const int* in_sizes, int n_in,
                              void* d_out, int out_size)
{
    const float* x      = (const float*)d_in[0];
    const void*  ei     = d_in[1];
    const void*  batch  = d_in[2];
    const float* Wemb   = (const float*)d_in[3];
    const float* bemb   = (const float*)d_in[4];
    const float* Wscore = (const float*)d_in[5];
    const float* bscore = (const float*)d_in[6];
    const float* Wfwd   = (const float*)d_in[7];
    const float* Wbwd   = (const float*)d_in[8];
    const float* Wself  = (const float*)d_in[9];
    const float* bself  = (const float*)d_in[10];
    const float* Wcomb  = (const float*)d_in[11];
    const float* bcomb  = (const float*)d_in[12];
    const float* gamma  = (const float*)d_in[13];
    const float* beta   = (const float*)d_in[14];
    float* out = (float*)d_out;

    float *pH, *pZ, *pAF, *pAB, *pS, *pM, *pBC;
    int *pDeg, *pOff, *pCur, *pSrcE, *pDstE, *pSrcS;
    cudaGetSymbolAddress((void**)&pH,  g_h);
    cudaGetSymbolAddress((void**)&pZ,  g_z);
    cudaGetSymbolAddress((void**)&pAF, g_aF);
    cudaGetSymbolAddress((void**)&pAB, g_aB);
    cudaGetSymbolAddress((void**)&pS,  g_scores);
    cudaGetSymbolAddress((void**)&pM,  g_M);
    cudaGetSymbolAddress((void**)&pBC, g_bc);
    cudaGetSymbolAddress((void**)&pDeg,  g_deg);
    cudaGetSymbolAddress((void**)&pOff,  g_off);
    cudaGetSymbolAddress((void**)&pCur,  g_cur);
    cudaGetSymbolAddress((void**)&pSrcE, g_srcE);
    cudaGetSymbolAddress((void**)&pDstE, g_dstE);
    cudaGetSymbolAddress((void**)&pSrcS, g_srcS);

    const int smemBytes = GSMEM_FLOATS * sizeof(float);
    cudaFuncSetAttribute(gemm3_kernel, cudaFuncAttributeMaxDynamicSharedMemorySize, smemBytes);

    const int gemmBlocks = (N_NODES + 63) / 64;
    const int warpBlocks = (N_NODES + 7) / 8;
    const int edgeThBlocks = (N_EDGES + 255) / 256;

    detect_kernel<<<1, 256>>>((const unsigned int*)ei);

    // CSR build (once per launch, reused for all 3 layers)
    zero_int_kernel<<<(N_NODES + 255) / 256, 256>>>(pDeg, N_NODES);
    count_kernel<<<edgeThBlocks, 256>>>(ei, pDeg, pSrcE, pDstE);
    scan_kernel<<<1, 1024>>>(pDeg, pOff, pCur);
    scatter_kernel<<<edgeThBlocks, 256>>>(pSrcE, pDstE, pCur, pSrcS);

    prep_M_kernel<<<72, 128>>>(Wcomb, Wself, Wfwd, Wbwd, pM);
    prep_b_kernel<<<N_LAYERS, 128>>>(Wcomb, bself, bcomb, pBC);

    // embed: h = relu(x @ Wemb^T + bemb)
    gemm3_kernel<<<gemmBlocks, 256, smemBytes>>>(x, Wemb, nullptr, nullptr, nullptr, nullptr,
                                                 bemb, pH, N_NODES, 1);
    scores_kernel<<<warpBlocks, 256>>>(pH, Wscore, bscore, pS, N_NODES);

    for (int l = 0; l < N_LAYERS; l++) {
        agg_kernel<<<warpBlocks, 256>>>(pOff, pSrcS, pS, pH, pAF, pAB);
        gemm3_kernel<<<gemmBlocks, 256, smemBytes>>>(
            pH,  pM + (l * 3 + 0) * DIM * DIM,
            pAF, pM + (l * 3 + 1) * DIM * DIM,
            pAB, pM + (l * 3 + 2) * DIM * DIM,
            pBC + l * DIM, pZ, N_NODES, 0);
        const float* wsc_next = (l + 1 < N_LAYERS) ? (Wscore + (l + 1) * DIM) : nullptr;
        const float* bsc_next = (l + 1 < N_LAYERS) ? (bscore + (l + 1)) : nullptr;
        ln_kernel<<<warpBlocks, 256>>>(pZ, gamma + l * DIM, beta + l * DIM, pH, N_NODES,
                                       wsc_next, bsc_next, pS);
    }

    zero_out_kernel<<<(N_GRAPHS * DIM + 255) / 256, 256>>>(out, N_GRAPHS * DIM);
    pool_kernel<<<dim3(N_GRAPHS, 8), DIM>>>(pH, batch, out);
}

// round 5
// speedup vs baseline: 1.3711x; 1.2053x over previous
#include <cuda_runtime.h>
#include <cuda_bf16.h>
#include <math.h>

#define N_NODES 50000
#define N_EDGES 625000
#define DIM 128
#define N_LAYERS 3
#define N_GRAPHS 64
#define LN_EPS 1e-5f

// ---------------- device scratch ----------------
__device__ float g_h[N_NODES * DIM];
__device__ float g_z[N_NODES * DIM];
__device__ float g_aF[N_NODES * DIM];
__device__ float g_aB[N_NODES * DIM];
__device__ float g_scores[N_NODES];
__device__ float g_M[9 * DIM * DIM];
__device__ float g_bc[N_LAYERS * DIM];
__device__ int   g_is64;
// CSR scratch
__device__ int g_deg[N_NODES];
__device__ int g_off[N_NODES + 1];
__device__ int g_cur[N_NODES];
__device__ int g_srcE[N_EDGES];
__device__ int g_dstE[N_EDGES];
__device__ int g_srcS[N_EDGES];
__device__ int g_bsum[256];

#define SCAN_BLOCKS ((N_NODES + 255) / 256)   // 196

// ---------------- dtype detection ----------------
__global__ void detect_kernel(const unsigned int* __restrict__ p)
{
    __shared__ int nz;
    if (threadIdx.x == 0) nz = 0;
    __syncthreads();
    for (int i = threadIdx.x; i < 4096; i += blockDim.x)
        if (p[2 * i + 1] != 0u) atomicOr(&nz, 1);
    __syncthreads();
    if (threadIdx.x == 0) g_is64 = nz ? 0 : 1;
}

__device__ __forceinline__ int load_idx(const void* buf, long long i)
{
    int v;
    if (g_is64) v = (int)((const long long*)buf)[i];
    else        v = ((const int*)buf)[i];
    v = v < 0 ? 0 : (v >= N_NODES ? N_NODES - 1 : v);
    return v;
}

// ---------------- CSR build ----------------
__global__ void zero_int_kernel(int* __restrict__ p, int n)
{
    int i = blockIdx.x * blockDim.x + threadIdx.x;
    if (i < n) p[i] = 0;
}

__global__ void count_kernel(const void* __restrict__ ei,
                             int* __restrict__ deg,
                             int* __restrict__ srcE,
                             int* __restrict__ dstE)
{
    int e = blockIdx.x * blockDim.x + threadIdx.x;
    if (e >= N_EDGES) return;
    int s = load_idx(ei, e);
    int d = load_idx(ei, (long long)N_EDGES + e);
    srcE[e] = s;
    dstE[e] = d;
    atomicAdd(&deg[d], 1);
}

// Stage 1: per-block local exclusive scan (196 blocks x 256)
__global__ void scan_local_kernel(const int* __restrict__ deg,
                                  int* __restrict__ off,
                                  int* __restrict__ bsum)
{
    __shared__ int tmp[256];
    int t = threadIdx.x;
    int node = blockIdx.x * 256 + t;
    int v = (node < N_NODES) ? deg[node] : 0;
    tmp[t] = v;
    __syncthreads();
    #pragma unroll
    for (int o = 1; o < 256; o <<= 1) {
        int u = (t >= o) ? tmp[t - o] : 0;
        __syncthreads();
        tmp[t] += u;
        __syncthreads();
    }
    if (node < N_NODES) off[node] = tmp[t] - v;   // exclusive
    if (t == 255) bsum[blockIdx.x] = tmp[255];
}

// Stage 2: single block scans the 196 block sums (in place -> exclusive)
__global__ void scan_bsum_kernel(int* __restrict__ bsum, int* __restrict__ off)
{
    __shared__ int tmp[256];
    int t = threadIdx.x;
    int v = (t < SCAN_BLOCKS) ? bsum[t] : 0;
    tmp[t] = v;
    __syncthreads();
    #pragma unroll
    for (int o = 1; o < 256; o <<= 1) {
        int u = (t >= o) ? tmp[t - o] : 0;
        __syncthreads();
        tmp[t] += u;
        __syncthreads();
    }
    if (t < SCAN_BLOCKS) bsum[t] = tmp[t] - v;    // exclusive
    if (t == 255) off[N_NODES] = tmp[255];        // total = E
}

// Stage 3: add block offsets, fill cur
__global__ void scan_add_kernel(int* __restrict__ off,
                                const int* __restrict__ bsum,
                                int* __restrict__ cur)
{
    int node = blockIdx.x * 256 + threadIdx.x;
    if (node >= N_NODES) return;
    int o = off[node] + bsum[blockIdx.x];
    off[node] = o;
    cur[node] = o;
}

__global__ void scatter_kernel(const int* __restrict__ srcE,
                               const int* __restrict__ dstE,
                               int* __restrict__ cur,
                               int* __restrict__ srcS)
{
    int e = blockIdx.x * blockDim.x + threadIdx.x;
    if (e >= N_EDGES) return;
    int pos = atomicAdd(&cur[dstE[e]], 1);
    srcS[pos] = srcE[e];
}

// ---------------- aggregation: warp per dst node, 4-wide ILP, no atomics ----------------
__global__ void agg_kernel(const int* __restrict__ off,
                           const int* __restrict__ srcS,
                           const float* __restrict__ scores,
                           const float* __restrict__ h,
                           float* __restrict__ aF,
                           float* __restrict__ aB)
{
    int node = (blockIdx.x * blockDim.x + threadIdx.x) >> 5;
    int lane = threadIdx.x & 31;
    if (node >= N_NODES) return;
    int lo = off[node], hi = off[node + 1];
    float sd = scores[node];
    const float4* h4 = reinterpret_cast<const float4*>(h);
    float4 af = make_float4(0.f, 0.f, 0.f, 0.f);
    float4 ab = make_float4(0.f, 0.f, 0.f, 0.f);
    int e = lo;
    for (; e + 4 <= hi; e += 4) {
        int s0 = srcS[e + 0], s1 = srcS[e + 1], s2 = srcS[e + 2], s3 = srcS[e + 3];
        float c0 = scores[s0], c1 = scores[s1], c2 = scores[s2], c3 = scores[s3];
        float4 v0 = h4[(size_t)s0 * 32 + lane];
        float4 v1 = h4[(size_t)s1 * 32 + lane];
        float4 v2 = h4[(size_t)s2 * 32 + lane];
        float4 v3 = h4[(size_t)s3 * 32 + lane];
        float a0 = 1.0f / (1.0f + __expf(sd - c0));
        float a1 = 1.0f / (1.0f + __expf(sd - c1));
        float a2 = 1.0f / (1.0f + __expf(sd - c2));
        float a3 = 1.0f / (1.0f + __expf(sd - c3));
        af.x += v0.x*a0 + v1.x*a1 + v2.x*a2 + v3.x*a3;
        af.y += v0.y*a0 + v1.y*a1 + v2.y*a2 + v3.y*a3;
        af.z += v0.z*a0 + v1.z*a1 + v2.z*a2 + v3.z*a3;
        af.w += v0.w*a0 + v1.w*a1 + v2.w*a2 + v3.w*a3;
        float b0 = 1.f-a0, b1 = 1.f-a1, b2 = 1.f-a2, b3 = 1.f-a3;
        ab.x += v0.x*b0 + v1.x*b1 + v2.x*b2 + v3.x*b3;
        ab.y += v0.y*b0 + v1.y*b1 + v2.y*b2 + v3.y*b3;
        ab.z += v0.z*b0 + v1.z*b1 + v2.z*b2 + v3.z*b3;
        ab.w += v0.w*b0 + v1.w*b1 + v2.w*b2 + v3.w*b3;
    }
    for (; e < hi; e++) {
        int s = srcS[e];
        float a = 1.0f / (1.0f + __expf(sd - scores[s]));
        float b = 1.0f - a;
        float4 v = h4[(size_t)s * 32 + lane];
        af.x += v.x*a; af.y += v.y*a; af.z += v.z*a; af.w += v.w*a;
        ab.x += v.x*b; ab.y += v.y*b; ab.z += v.z*b; ab.w += v.w*b;
    }
    reinterpret_cast<float4*>(aF + (size_t)node * DIM)[lane] = af;
    reinterpret_cast<float4*>(aB + (size_t)node * DIM)[lane] = ab;
}

// ---------------- prep: M_m = Wcomb_chunk_m @ W_m ----------------
__global__ void prep_M_kernel(const float* __restrict__ Wcomb,
                              const float* __restrict__ Wself,
                              const float* __restrict__ Wfwd,
                              const float* __restrict__ Wbwd,
                              float* __restrict__ M)
{
    int b = blockIdx.x;
    int rc = b & 7;
    int m  = (b >> 3) % 3;
    int l  = b / 24;
    const float* src = (m == 0) ? (Wself + l * DIM * DIM)
                   : (m == 1) ? (Wfwd + l * DIM * DIM)
                              : (Wbwd + l * DIM * DIM);
    int j = threadIdx.x;

    __shared__ float wcs[16][DIM];
    #pragma unroll
    for (int i = 0; i < 16; i++) {
        int row = rc * 16 + i;
        wcs[i][j] = Wcomb[l * DIM * 3 * DIM + row * 3 * DIM + m * DIM + j];
    }
    __syncthreads();

    float acc[16];
    #pragma unroll
    for (int i = 0; i < 16; i++) acc[i] = 0.0f;

    for (int k = 0; k < DIM; k++) {
        float w = src[k * DIM + j];
        #pragma unroll
        for (int i = 0; i < 16; i++) acc[i] += wcs[i][k] * w;
    }
    float* dst = M + (l * 3 + m) * DIM * DIM;
    #pragma unroll
    for (int i = 0; i < 16; i++) dst[(rc * 16 + i) * DIM + j] = acc[i];
}

__global__ void prep_b_kernel(const float* __restrict__ Wcomb,
                              const float* __restrict__ bself,
                              const float* __restrict__ bcomb,
                              float* __restrict__ bc)
{
    int l = blockIdx.x;
    int i = threadIdx.x;
    float s = bcomb[l * DIM + i];
    for (int k = 0; k < DIM; k++)
        s += Wcomb[l * DIM * 3 * DIM + i * 3 * DIM + k] * bself[l * DIM + k];
    bc[l * DIM + i] = s;
}

// ---------------- tiled GEMM, float4-vectorized with XOR-swizzled smem ----------------
// tiles stored k-major as float4 slots: tile4[row*32 + (k4 ^ (row & 31))]
// hs: 64 rows (nodes), ws: 128 rows (out cols). smem = (64+128)*32 float4 = 96KB.
#define GSMEM_BYTES ((64 + 128) * 32 * 16)
#define SWZ(k4, row) ((k4) ^ ((row) & 31))

__global__ void gemm3_kernel(const float* __restrict__ A0, const float* __restrict__ W0,
                             const float* __restrict__ A1, const float* __restrict__ W1,
                             const float* __restrict__ A2, const float* __restrict__ W2,
                             const float* __restrict__ bias,
                             float* __restrict__ out,
                             int n, int relu)
{
    extern __shared__ float4 sm4[];
    float4* hs4 = sm4;            // 64 * 32
    float4* ws4 = sm4 + 64 * 32;  // 128 * 32

    int tid = threadIdx.x;
    int tx = tid & 15;       // cols j = tx + 16q
    int ty = tid >> 4;       // rows ty*4 + r
    int base = blockIdx.x * 64;
    int ty4 = ty * 4;

    float acc[4][8];
    #pragma unroll
    for (int r = 0; r < 4; r++)
        #pragma unroll
        for (int q = 0; q < 8; q++) acc[r][q] = 0.0f;

    #pragma unroll
    for (int s = 0; s < 3; s++) {
        const float* A = (s == 0) ? A0 : (s == 1) ? A1 : A2;
        const float* W = (s == 0) ? W0 : (s == 1) ? W1 : W2;
        if (A == nullptr) continue;

        __syncthreads();
        // node tile: 64 rows x 32 slots; warp lane = k4 -> swizzled slots distinct
        #pragma unroll
        for (int it = 0; it < 8; it++) {
            int i = tid + it * 256;
            int nloc = i >> 5;
            int k4 = i & 31;
            int gn = base + nloc;
            float4 v = make_float4(0.f, 0.f, 0.f, 0.f);
            if (gn < n)
                v = *reinterpret_cast<const float4*>(A + (size_t)gn * DIM + k4 * 4);
            hs4[nloc * 32 + SWZ(k4, nloc)] = v;
        }
        // W tile: 128 rows x 32 slots
        #pragma unroll
        for (int it = 0; it < 16; it++) {
            int i = tid + it * 256;
            int j = i >> 5;
            int k4 = i & 31;
            float4 v = *reinterpret_cast<const float4*>(W + (size_t)j * DIM + k4 * 4);
            ws4[j * 32 + SWZ(k4, j)] = v;
        }
        __syncthreads();

        #pragma unroll 4
        for (int k4 = 0; k4 < 32; k4++) {
            float4 a[4];
            #pragma unroll
            for (int r = 0; r < 4; r++)
                a[r] = hs4[(ty4 + r) * 32 + SWZ(k4, ty4 + r)];
            #pragma unroll
            for (int q = 0; q < 8; q++) {
                int j = tx + 16 * q;
                float4 w = ws4[j * 32 + SWZ(k4, j)];
                #pragma unroll
                for (int r = 0; r < 4; r++)
                    acc[r][q] += a[r].x * w.x + a[r].y * w.y + a[r].z * w.z + a[r].w * w.w;
            }
        }
    }

    #pragma unroll
    for (int r = 0; r < 4; r++) {
        int gn = base + ty4 + r;
        if (gn >= n) continue;
        #pragma unroll
        for (int q = 0; q < 8; q++) {
            int j = tx + 16 * q;
            float v = acc[r][q];
            if (bias) v += bias[j];
            if (relu) v = fmaxf(v, 0.0f);
            out[(size_t)gn * DIM + j] = v;
        }
    }
}

// ---------------- scores (layer 0 only) ----------------
__global__ void scores_kernel(const float* __restrict__ h,
                              const float* __restrict__ wsc,
                              const float* __restrict__ bsc,
                              float* __restrict__ scores, int n)
{
    int wid = (blockIdx.x * blockDim.x + threadIdx.x) >> 5;
    int lane = threadIdx.x & 31;
    if (wid >= n) return;
    float4 hv = reinterpret_cast<const float4*>(h + (size_t)wid * DIM)[lane];
    float4 wv = reinterpret_cast<const float4*>(wsc)[lane];
    float p = hv.x * wv.x + hv.y * wv.y + hv.z * wv.z + hv.w * wv.w;
    #pragma unroll
    for (int o = 16; o > 0; o >>= 1) p += __shfl_xor_sync(0xFFFFFFFFu, p, o);
    if (lane == 0) scores[wid] = p + bsc[0];
}

// ---------------- LayerNorm + relu + residual (+ fused next-layer scores) ----------------
__global__ void ln_kernel(const float* __restrict__ z,
                          const float* __restrict__ gamma,
                          const float* __restrict__ beta,
                          float* __restrict__ h, int n,
                          const float* __restrict__ wsc,
                          const float* __restrict__ bsc,
                          float* __restrict__ scoresOut)
{
    int wid = (blockIdx.x * blockDim.x + threadIdx.x) >> 5;
    int lane = threadIdx.x & 31;
    if (wid >= n) return;
    float4 zv = reinterpret_cast<const float4*>(z + (size_t)wid * DIM)[lane];
    float s = zv.x + zv.y + zv.z + zv.w;
    #pragma unroll
    for (int o = 16; o > 0; o >>= 1) s += __shfl_xor_sync(0xFFFFFFFFu, s, o);
    float mu = s * (1.0f / 128.0f);
    float dx = zv.x - mu, dy = zv.y - mu, dz = zv.z - mu, dw = zv.w - mu;
    float q = dx * dx + dy * dy + dz * dz + dw * dw;
    #pragma unroll
    for (int o = 16; o > 0; o >>= 1) q += __shfl_xor_sync(0xFFFFFFFFu, q, o);
    float rs = rsqrtf(q * (1.0f / 128.0f) + LN_EPS);
    float4 g = reinterpret_cast<const float4*>(gamma)[lane];
    float4 b = reinterpret_cast<const float4*>(beta)[lane];
    float4* hp = reinterpret_cast<float4*>(h + (size_t)wid * DIM);
    float4 hv = hp[lane];
    float4 r;
    r.x = fmaxf(dx * rs * g.x + b.x, 0.0f) + hv.x;
    r.y = fmaxf(dy * rs * g.y + b.y, 0.0f) + hv.y;
    r.z = fmaxf(dz * rs * g.z + b.z, 0.0f) + hv.z;
    r.w = fmaxf(dw * rs * g.w + b.w, 0.0f) + hv.w;
    hp[lane] = r;

    if (wsc) {
        float4 wv = reinterpret_cast<const float4*>(wsc)[lane];
        float p = r.x * wv.x + r.y * wv.y + r.z * wv.z + r.w * wv.w;
        #pragma unroll
        for (int o = 16; o > 0; o >>= 1) p += __shfl_xor_sync(0xFFFFFFFFu, p, o);
        if (lane == 0) scoresOut[wid] = p + bsc[0];
    }
}

// ---------------- pool ----------------
__device__ __forceinline__ int lb_idx(const void* buf, int n, int val)
{
    int lo = 0, hi = n;
    while (lo < hi) {
        int mid = (lo + hi) >> 1;
        int bv;
        if (g_is64) bv = (int)((const long long*)buf)[mid];
        else        bv = ((const int*)buf)[mid];
        if (bv < val) lo = mid + 1; else hi = mid;
    }
    return lo;
}

__global__ void zero_out_kernel(float* __restrict__ p, int n)
{
    int i = blockIdx.x * blockDim.x + threadIdx.x;
    if (i < n) p[i] = 0.0f;
}

__global__ void pool_kernel(const float* __restrict__ h,
                            const void* __restrict__ batch,
                            float* __restrict__ out)
{
    int g = blockIdx.x;
    int slice = blockIdx.y;
    int j = threadIdx.x;
    __shared__ int s_lo, s_hi;
    if (j == 0) {
        s_lo = lb_idx(batch, N_NODES, g);
        s_hi = lb_idx(batch, N_NODES, g + 1);
    }
    __syncthreads();
    float sum = 0.0f;
    for (int nd = s_lo + slice; nd < s_hi; nd += 8)
        sum += h[(size_t)nd * DIM + j];
    float c = fmaxf((float)(s_hi - s_lo), 1.0f);
    atomicAdd(&out[g * DIM + j], sum / c);
}

// ---------------- launch ----------------
extern "C" void kernel_launch(void* const* d_in, const int* in_sizes, int n_in,
                              void* d_out, int out_size)
{
    const float* x      = (const float*)d_in[0];
    const void*  ei     = d_in[1];
    const void*  batch  = d_in[2];
    const float* Wemb   = (const float*)d_in[3];
    const float* bemb   = (const float*)d_in[4];
    const float* Wscore = (const float*)d_in[5];
    const float* bscore = (const float*)d_in[6];
    const float* Wfwd   = (const float*)d_in[7];
    const float* Wbwd   = (const float*)d_in[8];
    const float* Wself  = (const float*)d_in[9];
    const float* bself  = (const float*)d_in[10];
    const float* Wcomb  = (const float*)d_in[11];
    const float* bcomb  = (const float*)d_in[12];
    const float* gamma  = (const float*)d_in[13];
    const float* beta   = (const float*)d_in[14];
    float* out = (float*)d_out;

    float *pH, *pZ, *pAF, *pAB, *pS, *pM, *pBC;
    int *pDeg, *pOff, *pCur, *pSrcE, *pDstE, *pSrcS, *pBsum;
    cudaGetSymbolAddress((void**)&pH,  g_h);
    cudaGetSymbolAddress((void**)&pZ,  g_z);
    cudaGetSymbolAddress((void**)&pAF, g_aF);
    cudaGetSymbolAddress((void**)&pAB, g_aB);
    cudaGetSymbolAddress((void**)&pS,  g_scores);
    cudaGetSymbolAddress((void**)&pM,  g_M);
    cudaGetSymbolAddress((void**)&pBC, g_bc);
    cudaGetSymbolAddress((void**)&pDeg,  g_deg);
    cudaGetSymbolAddress((void**)&pOff,  g_off);
    cudaGetSymbolAddress((void**)&pCur,  g_cur);
    cudaGetSymbolAddress((void**)&pSrcE, g_srcE);
    cudaGetSymbolAddress((void**)&pDstE, g_dstE);
    cudaGetSymbolAddress((void**)&pSrcS, g_srcS);
    cudaGetSymbolAddress((void**)&pBsum, g_bsum);

    cudaFuncSetAttribute(gemm3_kernel, cudaFuncAttributeMaxDynamicSharedMemorySize, GSMEM_BYTES);

    const int gemmBlocks = (N_NODES + 63) / 64;
    const int warpBlocks = (N_NODES + 7) / 8;
    const int edgeThBlocks = (N_EDGES + 255) / 256;

    detect_kernel<<<1, 256>>>((const unsigned int*)ei);

    // CSR build (once, reused all 3 layers)
    zero_int_kernel<<<(N_NODES + 255) / 256, 256>>>(pDeg, N_NODES);
    count_kernel<<<edgeThBlocks, 256>>>(ei, pDeg, pSrcE, pDstE);
    scan_local_kernel<<<SCAN_BLOCKS, 256>>>(pDeg, pOff, pBsum);
    scan_bsum_kernel<<<1, 256>>>(pBsum, pOff);
    scan_add_kernel<<<SCAN_BLOCKS, 256>>>(pOff, pBsum, pCur);
    scatter_kernel<<<edgeThBlocks, 256>>>(pSrcE, pDstE, pCur, pSrcS);

    prep_M_kernel<<<72, 128>>>(Wcomb, Wself, Wfwd, Wbwd, pM);
    prep_b_kernel<<<N_LAYERS, 128>>>(Wcomb, bself, bcomb, pBC);

    // embed: h = relu(x @ Wemb^T + bemb)
    gemm3_kernel<<<gemmBlocks, 256, GSMEM_BYTES>>>(x, Wemb, nullptr, nullptr, nullptr, nullptr,
                                                   bemb, pH, N_NODES, 1);
    scores_kernel<<<warpBlocks, 256>>>(pH, Wscore, bscore, pS, N_NODES);

    for (int l = 0; l < N_LAYERS; l++) {
        agg_kernel<<<warpBlocks, 256>>>(pOff, pSrcS, pS, pH, pAF, pAB);
        gemm3_kernel<<<gemmBlocks, 256, GSMEM_BYTES>>>(
            pH,  pM + (l * 3 + 0) * DIM * DIM,
            pAF, pM + (l * 3 + 1) * DIM * DIM,
            pAB, pM + (l * 3 + 2) * DIM * DIM,
            pBC + l * DIM, pZ, N_NODES, 0);
        const float* wsc_next = (l + 1 < N_LAYERS) ? (Wscore + (l + 1) * DIM) : nullptr;
        const float* bsc_next = (l + 1 < N_LAYERS) ? (bscore + (l + 1)) : nullptr;
        ln_kernel<<<warpBlocks, 256>>>(pZ, gamma + l * DIM, beta + l * DIM, pH, N_NODES,
                                       wsc_next, bsc_next, pS);
    }

    zero_out_kernel<<<(N_GRAPHS * DIM + 255) / 256, 256>>>(out, N_GRAPHS * DIM);
    pool_kernel<<<dim3(N_GRAPHS, 8), DIM>>>(pH, batch, out);
}

// round 7
// speedup vs baseline: 1.6912x; 1.2335x over previous
#include <cuda_runtime.h>
#include <cuda_bf16.h>
#include <math.h>
#include <stdint.h>

#define N_NODES 50000
#define N_EDGES 625000
#define DIM 128
#define N_LAYERS 3
#define N_GRAPHS 64
#define LN_EPS 1e-5f

__device__ __forceinline__ uint32_t smem_to_u32(const void* smem_ptr) {
    uint32_t addr;
    asm("{ .reg .u64 tmp; cvta.to.shared.u64 tmp, %1; cvt.u32.u64 %0, tmp; }"
        : "=r"(addr) : "l"(smem_ptr));
    return addr;
}

// ---- warp MMA primitives (baseline PTX, sm_80+: compiles for compute_103) ----
#define LDSM_X4(r, addr) \
    asm volatile("ldmatrix.sync.aligned.m8n8.x4.shared.b16 {%0,%1,%2,%3}, [%4];" \
        : "=r"((r)[0]), "=r"((r)[1]), "=r"((r)[2]), "=r"((r)[3]) : "r"(addr))
#define LDSM_X2(r, addr) \
    asm volatile("ldmatrix.sync.aligned.m8n8.x2.shared.b16 {%0,%1}, [%2];" \
        : "=r"((r)[0]), "=r"((r)[1]) : "r"(addr))
#define MMA16816(d, a, b) \
    asm volatile("mma.sync.aligned.m16n8k16.row.col.f32.bf16.bf16.f32 " \
        "{%0,%1,%2,%3}, {%4,%5,%6,%7}, {%8,%9}, {%0,%1,%2,%3};" \
        : "+f"((d)[0]), "+f"((d)[1]), "+f"((d)[2]), "+f"((d)[3]) \
        : "r"((a)[0]), "r"((a)[1]), "r"((a)[2]), "r"((a)[3]), \
          "r"((b)[0]), "r"((b)[1]))

// ================= device scratch =================
__device__ float g_h[N_NODES * DIM];
__device__ float g_aF[N_NODES * DIM];
__device__ float g_aB[N_NODES * DIM];
__device__ float g_scores[N_NODES];
__device__ float g_M[9 * DIM * DIM];
__device__ float g_bc[N_LAYERS * DIM];
__device__ __nv_bfloat16 g_Wh[10 * DIM * DIM];  // mat0=Wemb, 1..9 = fused M
__device__ __nv_bfloat16 g_Wl[10 * DIM * DIM];
__device__ int g_is64;
// CSR
__device__ int g_deg[N_NODES];
__device__ int g_off[N_NODES + 1];
__device__ int g_cur[N_NODES];
__device__ int g_srcE[N_EDGES];
__device__ int g_dstE[N_EDGES];
__device__ int g_srcS[N_EDGES];
__device__ int g_bsum[256];

#define SCAN_BLOCKS ((N_NODES + 255) / 256)

// ================= dtype detection =================
__global__ void detect_kernel(const unsigned int* __restrict__ p)
{
    __shared__ int nz;
    if (threadIdx.x == 0) nz = 0;
    __syncthreads();
    for (int i = threadIdx.x; i < 4096; i += blockDim.x)
        if (p[2 * i + 1] != 0u) atomicOr(&nz, 1);
    __syncthreads();
    if (threadIdx.x == 0) g_is64 = nz ? 0 : 1;
}

__device__ __forceinline__ int load_idx(const void* buf, long long i)
{
    int v;
    if (g_is64) v = (int)((const long long*)buf)[i];
    else        v = ((const int*)buf)[i];
    v = v < 0 ? 0 : (v >= N_NODES ? N_NODES - 1 : v);
    return v;
}

// ================= CSR build =================
__global__ void zero_int_kernel(int* __restrict__ p, int n)
{
    int i = blockIdx.x * blockDim.x + threadIdx.x;
    if (i < n) p[i] = 0;
}

__global__ void count_kernel(const void* __restrict__ ei,
                             int* __restrict__ deg,
                             int* __restrict__ srcE,
                             int* __restrict__ dstE)
{
    int e = blockIdx.x * blockDim.x + threadIdx.x;
    if (e >= N_EDGES) return;
    int s = load_idx(ei, e);
    int d = load_idx(ei, (long long)N_EDGES + e);
    srcE[e] = s;
    dstE[e] = d;
    atomicAdd(&deg[d], 1);
}

__global__ void scan_local_kernel(const int* __restrict__ deg,
                                  int* __restrict__ off,
                                  int* __restrict__ bsum)
{
    __shared__ int tmp[256];
    int t = threadIdx.x;
    int node = blockIdx.x * 256 + t;
    int v = (node < N_NODES) ? deg[node] : 0;
    tmp[t] = v;
    __syncthreads();
    #pragma unroll
    for (int o = 1; o < 256; o <<= 1) {
        int u = (t >= o) ? tmp[t - o] : 0;
        __syncthreads();
        tmp[t] += u;
        __syncthreads();
    }
    if (node < N_NODES) off[node] = tmp[t] - v;
    if (t == 255) bsum[blockIdx.x] = tmp[255];
}

__global__ void scan_bsum_kernel(int* __restrict__ bsum, int* __restrict__ off)
{
    __shared__ int tmp[256];
    int t = threadIdx.x;
    int v = (t < SCAN_BLOCKS) ? bsum[t] : 0;
    tmp[t] = v;
    __syncthreads();
    #pragma unroll
    for (int o = 1; o < 256; o <<= 1) {
        int u = (t >= o) ? tmp[t - o] : 0;
        __syncthreads();
        tmp[t] += u;
        __syncthreads();
    }
    if (t < SCAN_BLOCKS) bsum[t] = tmp[t] - v;
    if (t == 255) off[N_NODES] = tmp[255];
}

__global__ void scan_add_kernel(int* __restrict__ off,
                                const int* __restrict__ bsum,
                                int* __restrict__ cur)
{
    int node = blockIdx.x * 256 + threadIdx.x;
    if (node >= N_NODES) return;
    int o = off[node] + bsum[blockIdx.x];
    off[node] = o;
    cur[node] = o;
}

__global__ void scatter_kernel(const int* __restrict__ srcE,
                               const int* __restrict__ dstE,
                               int* __restrict__ cur,
                               int* __restrict__ srcS)
{
    int e = blockIdx.x * blockDim.x + threadIdx.x;
    if (e >= N_EDGES) return;
    int pos = atomicAdd(&cur[dstE[e]], 1);
    srcS[pos] = srcE[e];
}

// ================= aggregation (warp per dst node) =================
__global__ void agg_kernel(const int* __restrict__ off,
                           const int* __restrict__ srcS,
                           const float* __restrict__ scores,
                           const float* __restrict__ h,
                           float* __restrict__ aF,
                           float* __restrict__ aB)
{
    int node = (blockIdx.x * blockDim.x + threadIdx.x) >> 5;
    int lane = threadIdx.x & 31;
    if (node >= N_NODES) return;
    int lo = off[node], hi = off[node + 1];
    float sd = scores[node];
    const float4* h4 = reinterpret_cast<const float4*>(h);
    float4 af = make_float4(0.f, 0.f, 0.f, 0.f);
    float4 ab = make_float4(0.f, 0.f, 0.f, 0.f);
    int e = lo;
    for (; e + 4 <= hi; e += 4) {
        int s0 = srcS[e + 0], s1 = srcS[e + 1], s2 = srcS[e + 2], s3 = srcS[e + 3];
        float c0 = scores[s0], c1 = scores[s1], c2 = scores[s2], c3 = scores[s3];
        float4 v0 = h4[(size_t)s0 * 32 + lane];
        float4 v1 = h4[(size_t)s1 * 32 + lane];
        float4 v2 = h4[(size_t)s2 * 32 + lane];
        float4 v3 = h4[(size_t)s3 * 32 + lane];
        float a0 = 1.0f / (1.0f + __expf(sd - c0));
        float a1 = 1.0f / (1.0f + __expf(sd - c1));
        float a2 = 1.0f / (1.0f + __expf(sd - c2));
        float a3 = 1.0f / (1.0f + __expf(sd - c3));
        af.x += v0.x*a0 + v1.x*a1 + v2.x*a2 + v3.x*a3;
        af.y += v0.y*a0 + v1.y*a1 + v2.y*a2 + v3.y*a3;
        af.z += v0.z*a0 + v1.z*a1 + v2.z*a2 + v3.z*a3;
        af.w += v0.w*a0 + v1.w*a1 + v2.w*a2 + v3.w*a3;
        float b0 = 1.f-a0, b1 = 1.f-a1, b2 = 1.f-a2, b3 = 1.f-a3;
        ab.x += v0.x*b0 + v1.x*b1 + v2.x*b2 + v3.x*b3;
        ab.y += v0.y*b0 + v1.y*b1 + v2.y*b2 + v3.y*b3;
        ab.z += v0.z*b0 + v1.z*b1 + v2.z*b2 + v3.z*b3;
        ab.w += v0.w*b0 + v1.w*b1 + v2.w*b2 + v3.w*b3;
    }
    for (; e < hi; e++) {
        int s = srcS[e];
        float a = 1.0f / (1.0f + __expf(sd - scores[s]));
        float b = 1.0f - a;
        float4 v = h4[(size_t)s * 32 + lane];
        af.x += v.x*a; af.y += v.y*a; af.z += v.z*a; af.w += v.w*a;
        ab.x += v.x*b; ab.y += v.y*b; ab.z += v.z*b; ab.w += v.w*b;
    }
    reinterpret_cast<float4*>(aF + (size_t)node * DIM)[lane] = af;
    reinterpret_cast<float4*>(aB + (size_t)node * DIM)[lane] = ab;
}

// ================= prep kernels =================
__global__ void prep_M_kernel(const float* __restrict__ Wcomb,
                              const float* __restrict__ Wself,
                              const float* __restrict__ Wfwd,
                              const float* __restrict__ Wbwd,
                              float* __restrict__ M)
{
    int b = blockIdx.x;
    int rc = b & 7;
    int m  = (b >> 3) % 3;
    int l  = b / 24;
    const float* src = (m == 0) ? (Wself + l * DIM * DIM)
                   : (m == 1) ? (Wfwd + l * DIM * DIM)
                              : (Wbwd + l * DIM * DIM);
    int j = threadIdx.x;

    __shared__ float wcs[16][DIM];
    #pragma unroll
    for (int i = 0; i < 16; i++) {
        int row = rc * 16 + i;
        wcs[i][j] = Wcomb[l * DIM * 3 * DIM + row * 3 * DIM + m * DIM + j];
    }
    __syncthreads();

    float acc[16];
    #pragma unroll
    for (int i = 0; i < 16; i++) acc[i] = 0.0f;
    for (int k = 0; k < DIM; k++) {
        float w = src[k * DIM + j];
        #pragma unroll
        for (int i = 0; i < 16; i++) acc[i] += wcs[i][k] * w;
    }
    float* dst = M + (l * 3 + m) * DIM * DIM;
    #pragma unroll
    for (int i = 0; i < 16; i++) dst[(rc * 16 + i) * DIM + j] = acc[i];
}

__global__ void prep_b_kernel(const float* __restrict__ Wcomb,
                              const float* __restrict__ bself,
                              const float* __restrict__ bcomb,
                              float* __restrict__ bc)
{
    int l = blockIdx.x;
    int i = threadIdx.x;
    float s = bcomb[l * DIM + i];
    for (int k = 0; k < DIM; k++)
        s += Wcomb[l * DIM * 3 * DIM + i * 3 * DIM + k] * bself[l * DIM + k];
    bc[l * DIM + i] = s;
}

// convert Wemb (mat 0) + fused M (mats 1..9) to bf16 hi/lo
__global__ void prep_Wbf_kernel(const float* __restrict__ Wemb,
                                const float* __restrict__ M,
                                __nv_bfloat16* __restrict__ Wh,
                                __nv_bfloat16* __restrict__ Wl)
{
    int idx = blockIdx.x * blockDim.x + threadIdx.x;
    if (idx >= 10 * DIM * DIM) return;
    int mat = idx / (DIM * DIM);
    int rem = idx % (DIM * DIM);
    float w = (mat == 0) ? Wemb[rem] : M[(mat - 1) * DIM * DIM + rem];
    __nv_bfloat16 hi = __float2bfloat16_rn(w);
    float lo = w - __bfloat162float(hi);
    Wh[idx] = hi;
    Wl[idx] = __float2bfloat16_rn(lo);
}

// ================= tensor-core GEMM (mma.sync) + fused epilogue =================
// out[node,j] = sum_s sum_k A_s[node,k] * W_s[j,k]  via bf16-split HMMA.
// mode 0: h = relu(out + bias)
// mode 1: h = relu(LN(out + bias)*gamma+beta) + h   (in-place on own tile rows)
// wsc != null: scores[node] = dot(h_new_row, wsc) + bscp[0]
//
// smem layout:
//   [0, 4096): ctrl  (bias 0, gamma 512, beta 1024, wsc 1536, mu 2048, rs 2560, sc 3072)
//   [4096, 77824): bf16 tiles during mainloop (AHI/ALO/WHI/WLO, 18432 B each,
//                  row stride 144 B, 128 rows x 64 k) — reused as fp32 accum
//                  tile (128 x 129 floats) in the epilogue.
#define OFF_BIAS  0
#define OFF_GAMMA 512
#define OFF_BETA  1024
#define OFF_WSC   1536
#define OFF_MU    2048
#define OFF_RS    2560
#define OFF_SC    3072
#define AHI_OFF   4096
#define ALO_OFF   (4096 + 18432)
#define WHI_OFF   (4096 + 36864)
#define WLO_OFF   (4096 + 55296)
#define MM_SMEM   (4096 + 73728)
#define BF_STRIDE 144

__global__ void __launch_bounds__(256)
mm_mma_kernel(const float* __restrict__ A0, const float* __restrict__ A1,
              const float* __restrict__ A2,
              const __nv_bfloat16* __restrict__ Whb,
              const __nv_bfloat16* __restrict__ Wlb,
              const float* __restrict__ bias,
              const float* __restrict__ gamma,
              const float* __restrict__ beta,
              const float* __restrict__ wsc,
              const float* __restrict__ bscp,
              float* __restrict__ hOut,
              float* __restrict__ scoresOut,
              int n, int nsrc, int mode)
{
    extern __shared__ char smem[];
    uint32_t smemU = smem_to_u32(smem);
    int tid = threadIdx.x;
    int lane = tid & 31;
    int warp = tid >> 5;
    int base = blockIdx.x * 128;

    float* bias_s  = (float*)(smem + OFF_BIAS);
    float* gamma_s = (float*)(smem + OFF_GAMMA);
    float* beta_s  = (float*)(smem + OFF_BETA);
    float* wsc_s   = (float*)(smem + OFF_WSC);
    float* mu_s    = (float*)(smem + OFF_MU);
    float* rs_s    = (float*)(smem + OFF_RS);
    float* sc_s    = (float*)(smem + OFF_SC);

    if (tid < 128) {
        bias_s[tid] = bias ? bias[tid] : 0.0f;
        if (mode == 1) { gamma_s[tid] = gamma[tid]; beta_s[tid] = beta[tid]; }
        if (wsc) wsc_s[tid] = wsc[tid];
        sc_s[tid] = 0.0f;
    }

    // warp tiling: 2 (m) x 4 (n) warps; warp owns 64x32 via 4x4 m16n8 tiles
    int mO = (warp >> 2) * 64;
    int nO = (warp & 3) * 32;
    // ldmatrix per-lane address components
    uint32_t aLaneOff = (uint32_t)((lane & 15) * BF_STRIDE + ((lane >> 4) << 4));
    uint32_t bLaneOff = (uint32_t)((lane & 7) * BF_STRIDE + (((lane >> 3) & 1) << 4));

    float acc[4][4][4];
    #pragma unroll
    for (int mt = 0; mt < 4; mt++)
        #pragma unroll
        for (int nt = 0; nt < 4; nt++)
            #pragma unroll
            for (int r = 0; r < 4; r++) acc[mt][nt][r] = 0.0f;

    const int nchunks = nsrc * 2;
    for (int c = 0; c < nchunks; c++) {
        int s = c >> 1;
        int half = c & 1;
        const float* A = (s == 0) ? A0 : (s == 1) ? A1 : A2;

        __syncthreads();   // tiles free (prev chunk's ldmatrix done)

        // --- convert A chunk: 128 rows x 64 k, fp32 -> bf16 hi/lo
        #pragma unroll
        for (int i = 0; i < 8; i++) {
            int idx = tid + i * 256;
            int row = idx >> 4;        // 0..127
            int k4  = idx & 15;        // float4 index within 64-k chunk
            int gn = base + row;
            float4 v = make_float4(0.f, 0.f, 0.f, 0.f);
            if (gn < n)
                v = *reinterpret_cast<const float4*>(A + (size_t)gn * DIM + half * 64 + k4 * 4);
            __nv_bfloat16 hx = __float2bfloat16_rn(v.x);
            __nv_bfloat16 hy = __float2bfloat16_rn(v.y);
            __nv_bfloat16 hz = __float2bfloat16_rn(v.z);
            __nv_bfloat16 hw = __float2bfloat16_rn(v.w);
            unsigned hi01 = (unsigned)__bfloat16_as_ushort(hx) |
                            ((unsigned)__bfloat16_as_ushort(hy) << 16);
            unsigned hi23 = (unsigned)__bfloat16_as_ushort(hz) |
                            ((unsigned)__bfloat16_as_ushort(hw) << 16);
            unsigned lo01 = (unsigned)__bfloat16_as_ushort(__float2bfloat16_rn(v.x - __bfloat162float(hx))) |
                            ((unsigned)__bfloat16_as_ushort(__float2bfloat16_rn(v.y - __bfloat162float(hy))) << 16);
            unsigned lo23 = (unsigned)__bfloat16_as_ushort(__float2bfloat16_rn(v.z - __bfloat162float(hz))) |
                            ((unsigned)__bfloat16_as_ushort(__float2bfloat16_rn(v.w - __bfloat162float(hw))) << 16);
            unsigned off = row * BF_STRIDE + k4 * 8;
            *(unsigned*)(smem + AHI_OFF + off)     = hi01;
            *(unsigned*)(smem + AHI_OFF + off + 4) = hi23;
            *(unsigned*)(smem + ALO_OFF + off)     = lo01;
            *(unsigned*)(smem + ALO_OFF + off + 4) = lo23;
        }
        // --- copy W chunk (bf16x2 words)
        const unsigned* WhU = (const unsigned*)(Whb + (size_t)s * DIM * DIM);
        const unsigned* WlU = (const unsigned*)(Wlb + (size_t)s * DIM * DIM);
        #pragma unroll
        for (int i = 0; i < 16; i++) {
            int idx = tid + i * 256;
            int row = idx >> 5;        // 0..127
            int w32 = idx & 31;        // u32 within 64-k chunk
            unsigned off = row * BF_STRIDE + w32 * 4;
            *(unsigned*)(smem + WHI_OFF + off) = WhU[row * 64 + half * 32 + w32];
            *(unsigned*)(smem + WLO_OFF + off) = WlU[row * 64 + half * 32 + w32];
        }
        __syncthreads();

        // --- MMA: 4 k16-steps x (4 mt x 4 nt) x 3 split terms
        #pragma unroll
        for (int ks = 0; ks < 4; ks++) {
            uint32_t kb2 = ks * 32;   // 16 bf16 * 2 bytes
            uint32_t ahi[4][4], alo[4][4];
            #pragma unroll
            for (int mt = 0; mt < 4; mt++) {
                uint32_t addr = smemU + AHI_OFF + (mO + mt * 16) * BF_STRIDE + kb2 + aLaneOff;
                LDSM_X4(ahi[mt], addr);
                LDSM_X4(alo[mt], addr + (ALO_OFF - AHI_OFF));
            }
            uint32_t bhi[4][2], blo[4][2];
            #pragma unroll
            for (int nt = 0; nt < 4; nt++) {
                uint32_t addr = smemU + WHI_OFF + (nO + nt * 8) * BF_STRIDE + kb2 + bLaneOff;
                LDSM_X2(bhi[nt], addr);
                LDSM_X2(blo[nt], addr + (WLO_OFF - WHI_OFF));
            }
            #pragma unroll
            for (int mt = 0; mt < 4; mt++)
                #pragma unroll
                for (int nt = 0; nt < 4; nt++) {
                    MMA16816(acc[mt][nt], ahi[mt], bhi[nt]);
                    MMA16816(acc[mt][nt], ahi[mt], blo[nt]);
                    MMA16816(acc[mt][nt], alo[mt], bhi[nt]);
                }
        }
    }
    __syncthreads();   // all warps done with tiles

    // ---------------- epilogue ----------------
    float* acc_sm = (float*)(smem + AHI_OFF);   // 128 x 129 fp32, reuses tiles
    #pragma unroll
    for (int mt = 0; mt < 4; mt++)
        #pragma unroll
        for (int nt = 0; nt < 4; nt++) {
            int R = mO + mt * 16 + (lane >> 2);
            int C = nO + nt * 8 + 2 * (lane & 3);
            acc_sm[R * 129 + C]           = acc[mt][nt][0];
            acc_sm[R * 129 + C + 1]       = acc[mt][nt][1];
            acc_sm[(R + 8) * 129 + C]     = acc[mt][nt][2];
            acc_sm[(R + 8) * 129 + C + 1] = acc[mt][nt][3];
        }
    __syncthreads();

    if (mode == 1 && tid < 128) {
        int r = tid;
        float sum = 0.0f, sq = 0.0f;
        #pragma unroll 4
        for (int j = 0; j < 128; j++) {
            float v = acc_sm[r * 129 + j] + bias_s[j];
            sum += v;
            sq  += v * v;
        }
        float mu = sum * (1.0f / 128.0f);
        mu_s[r] = mu;
        rs_s[r] = rsqrtf(fmaxf(sq * (1.0f / 128.0f) - mu * mu, 0.0f) + LN_EPS);
    }
    __syncthreads();

    // coalesced fused elementwise pass
    #pragma unroll 2
    for (int i = 0; i < 64; i++) {
        int idx = i * 256 + tid;
        int r = idx >> 7;
        int j = idx & 127;
        int gn = base + r;
        float v = acc_sm[r * 129 + j] + bias_s[j];
        float rnew;
        if (mode == 1) {
            float dn = (v - mu_s[r]) * rs_s[r];
            float idv = (gn < n) ? hOut[(size_t)gn * DIM + j] : 0.0f;
            rnew = fmaxf(dn * gamma_s[j] + beta_s[j], 0.0f) + idv;
        } else {
            rnew = fmaxf(v, 0.0f);
        }
        if (gn < n) hOut[(size_t)gn * DIM + j] = rnew;
        if (wsc) {
            float p = rnew * wsc_s[j];
            #pragma unroll
            for (int o = 16; o > 0; o >>= 1) p += __shfl_xor_sync(0xFFFFFFFFu, p, o);
            if (lane == 0) atomicAdd(&sc_s[r], p);
        }
    }
    if (wsc) {
        __syncthreads();
        if (tid < 128 && base + tid < n)
            scoresOut[base + tid] = sc_s[tid] + bscp[0];
    }
}

// ================= pool =================
__device__ __forceinline__ int lb_idx(const void* buf, int n, int val)
{
    int lo = 0, hi = n;
    while (lo < hi) {
        int mid = (lo + hi) >> 1;
        int bv;
        if (g_is64) bv = (int)((const long long*)buf)[mid];
        else        bv = ((const int*)buf)[mid];
        if (bv < val) lo = mid + 1; else hi = mid;
    }
    return lo;
}

__global__ void zero_out_kernel(float* __restrict__ p, int n)
{
    int i = blockIdx.x * blockDim.x + threadIdx.x;
    if (i < n) p[i] = 0.0f;
}

__global__ void pool_kernel(const float* __restrict__ h,
                            const void* __restrict__ batch,
                            float* __restrict__ out)
{
    int g = blockIdx.x;
    int slice = blockIdx.y;
    int j = threadIdx.x;
    __shared__ int s_lo, s_hi;
    if (j == 0) {
        s_lo = lb_idx(batch, N_NODES, g);
        s_hi = lb_idx(batch, N_NODES, g + 1);
    }
    __syncthreads();
    float sum = 0.0f;
    for (int nd = s_lo + slice; nd < s_hi; nd += 8)
        sum += h[(size_t)nd * DIM + j];
    float c = fmaxf((float)(s_hi - s_lo), 1.0f);
    atomicAdd(&out[g * DIM + j], sum / c);
}

// ================= launch =================
extern "C" void kernel_launch(void* const* d_in, const int* in_sizes, int n_in,
                              void* d_out, int out_size)
{
    const float* x      = (const float*)d_in[0];
    const void*  ei     = d_in[1];
    const void*  batch  = d_in[2];
    const float* Wemb   = (const float*)d_in[3];
    const float* bemb   = (const float*)d_in[4];
    const float* Wscore = (const float*)d_in[5];
    const float* bscore = (const float*)d_in[6];
    const float* Wfwd   = (const float*)d_in[7];
    const float* Wbwd   = (const float*)d_in[8];
    const float* Wself  = (const float*)d_in[9];
    const float* bself  = (const float*)d_in[10];
    const float* Wcomb  = (const float*)d_in[11];
    const float* bcomb  = (const float*)d_in[12];
    const float* gamma  = (const float*)d_in[13];
    const float* beta   = (const float*)d_in[14];
    float* out = (float*)d_out;

    float *pH, *pAF, *pAB, *pS, *pM, *pBC;
    __nv_bfloat16 *pWh, *pWl;
    int *pDeg, *pOff, *pCur, *pSrcE, *pDstE, *pSrcS, *pBsum;
    cudaGetSymbolAddress((void**)&pH,  g_h);
    cudaGetSymbolAddress((void**)&pAF, g_aF);
    cudaGetSymbolAddress((void**)&pAB, g_aB);
    cudaGetSymbolAddress((void**)&pS,  g_scores);
    cudaGetSymbolAddress((void**)&pM,  g_M);
    cudaGetSymbolAddress((void**)&pBC, g_bc);
    cudaGetSymbolAddress((void**)&pWh, g_Wh);
    cudaGetSymbolAddress((void**)&pWl, g_Wl);
    cudaGetSymbolAddress((void**)&pDeg,  g_deg);
    cudaGetSymbolAddress((void**)&pOff,  g_off);
    cudaGetSymbolAddress((void**)&pCur,  g_cur);
    cudaGetSymbolAddress((void**)&pSrcE, g_srcE);
    cudaGetSymbolAddress((void**)&pDstE, g_dstE);
    cudaGetSymbolAddress((void**)&pSrcS, g_srcS);
    cudaGetSymbolAddress((void**)&pBsum, g_bsum);

    cudaFuncSetAttribute(mm_mma_kernel, cudaFuncAttributeMaxDynamicSharedMemorySize, MM_SMEM);

    const int tileBlocks = (N_NODES + 127) / 128;   // 391
    const int warpBlocks = (N_NODES + 7) / 8;
    const int edgeThBlocks = (N_EDGES + 255) / 256;

    detect_kernel<<<1, 256>>>((const unsigned int*)ei);

    // CSR build
    zero_int_kernel<<<(N_NODES + 255) / 256, 256>>>(pDeg, N_NODES);
    count_kernel<<<edgeThBlocks, 256>>>(ei, pDeg, pSrcE, pDstE);
    scan_local_kernel<<<SCAN_BLOCKS, 256>>>(pDeg, pOff, pBsum);
    scan_bsum_kernel<<<1, 256>>>(pBsum, pOff);
    scan_add_kernel<<<SCAN_BLOCKS, 256>>>(pOff, pBsum, pCur);
    scatter_kernel<<<edgeThBlocks, 256>>>(pSrcE, pDstE, pCur, pSrcS);

    // weight prep
    prep_M_kernel<<<72, 128>>>(Wcomb, Wself, Wfwd, Wbwd, pM);
    prep_b_kernel<<<N_LAYERS, 128>>>(Wcomb, bself, bcomb, pBC);
    prep_Wbf_kernel<<<(10 * DIM * DIM + 255) / 256, 256>>>(Wemb, pM, pWh, pWl);

    // embed: h = relu(x @ Wemb^T + bemb), fused layer-0 scores
    mm_mma_kernel<<<tileBlocks, 256, MM_SMEM>>>(
        x, nullptr, nullptr, pWh, pWl, bemb,
        nullptr, nullptr, Wscore, bscore,
        pH, pS, N_NODES, 1, 0);

    for (int l = 0; l < N_LAYERS; l++) {
        agg_kernel<<<warpBlocks, 256>>>(pOff, pSrcS, pS, pH, pAF, pAB);
        const float* wsc_next = (l + 1 < N_LAYERS) ? (Wscore + (l + 1) * DIM) : nullptr;
        const float* bsc_next = (l + 1 < N_LAYERS) ? (bscore + (l + 1)) : nullptr;
        mm_mma_kernel<<<tileBlocks, 256, MM_SMEM>>>(
            pH, pAF, pAB,
            pWh + (size_t)(1 + l * 3) * DIM * DIM,
            pWl + (size_t)(1 + l * 3) * DIM * DIM,
            pBC + l * DIM, gamma + l * DIM, beta + l * DIM,
            wsc_next, bsc_next,
            pH, pS, N_NODES, 3, 1);
    }

    zero_out_kernel<<<(N_GRAPHS * DIM + 255) / 256, 256>>>(out, N_GRAPHS * DIM);
    pool_kernel<<<dim3(N_GRAPHS, 8), DIM>>>(pH, batch, out);
}

// round 8
// speedup vs baseline: 2.0991x; 1.2412x over previous
#include <cuda_runtime.h>
#include <cuda_bf16.h>
#include <math.h>
#include <stdint.h>

#define N_NODES 50000
#define N_EDGES 625000
#define DIM 128
#define N_LAYERS 3
#define N_GRAPHS 64
#define LN_EPS 1e-5f

__device__ __forceinline__ uint32_t smem_to_u32(const void* smem_ptr) {
    uint32_t addr;
    asm("{ .reg .u64 tmp; cvta.to.shared.u64 tmp, %1; cvt.u32.u64 %0, tmp; }"
        : "=r"(addr) : "l"(smem_ptr));
    return addr;
}

// ---- warp MMA primitives (baseline PTX, sm_80+) ----
#define LDSM_X4(r, addr) \
    asm volatile("ldmatrix.sync.aligned.m8n8.x4.shared.b16 {%0,%1,%2,%3}, [%4];" \
        : "=r"((r)[0]), "=r"((r)[1]), "=r"((r)[2]), "=r"((r)[3]) : "r"(addr))
#define LDSM_X2(r, addr) \
    asm volatile("ldmatrix.sync.aligned.m8n8.x2.shared.b16 {%0,%1}, [%2];" \
        : "=r"((r)[0]), "=r"((r)[1]) : "r"(addr))
#define MMA16816(d, a, b) \
    asm volatile("mma.sync.aligned.m16n8k16.row.col.f32.bf16.bf16.f32 " \
        "{%0,%1,%2,%3}, {%4,%5,%6,%7}, {%8,%9}, {%0,%1,%2,%3};" \
        : "+f"((d)[0]), "+f"((d)[1]), "+f"((d)[2]), "+f"((d)[3]) \
        : "r"((a)[0]), "r"((a)[1]), "r"((a)[2]), "r"((a)[3]), \
          "r"((b)[0]), "r"((b)[1]))
#define CP_ASYNC16(dst, src) \
    asm volatile("cp.async.ca.shared.global [%0], [%1], 16;" \
        :: "r"(dst), "l"(src) : "memory")
#define CP_ASYNC_COMMIT() asm volatile("cp.async.commit_group;" ::: "memory")
#define CP_ASYNC_WAIT0()  asm volatile("cp.async.wait_group 0;" ::: "memory")

// packed f32x2 -> bf16x2 (lo elem = first operand? PTX: cvt.rn.bf16x2.f32 d, a, b -> d = {b, a} lo=b)
__device__ __forceinline__ unsigned cvt_bf16x2(float hi_elem, float lo_elem) {
    unsigned r;
    asm("cvt.rn.bf16x2.f32 %0, %1, %2;" : "=r"(r) : "f"(hi_elem), "f"(lo_elem));
    return r;
}

// ================= device scratch =================
__device__ float g_h[N_NODES * DIM];
__device__ float g_aF[N_NODES * DIM];
__device__ float g_aB[N_NODES * DIM];
__device__ float g_scores[N_NODES];
__device__ float g_M[9 * DIM * DIM];
__device__ float g_bc[N_LAYERS * DIM];
__device__ __nv_bfloat16 g_Wh[10 * DIM * DIM];
__device__ __nv_bfloat16 g_Wl[10 * DIM * DIM];
__device__ int g_is64;
// CSR
__device__ int g_deg[N_NODES];
__device__ int g_off[N_NODES + 1];
__device__ int g_cur[N_NODES];
__device__ int g_srcS[N_EDGES];
__device__ int g_bsum[256];

#define SCAN_BLOCKS ((N_NODES + 255) / 256)

// ================= dtype detection =================
__global__ void detect_kernel(const unsigned int* __restrict__ p)
{
    __shared__ int nz;
    if (threadIdx.x == 0) nz = 0;
    __syncthreads();
    for (int i = threadIdx.x; i < 4096; i += blockDim.x)
        if (p[2 * i + 1] != 0u) atomicOr(&nz, 1);
    __syncthreads();
    if (threadIdx.x == 0) g_is64 = nz ? 0 : 1;
}

__device__ __forceinline__ int load_idx(const void* buf, long long i)
{
    int v;
    if (g_is64) v = (int)((const long long*)buf)[i];
    else        v = ((const int*)buf)[i];
    v = v < 0 ? 0 : (v >= N_NODES ? N_NODES - 1 : v);
    return v;
}

// ================= CSR build =================
__global__ void zero_int_kernel(int* __restrict__ p, int n)
{
    int i = blockIdx.x * blockDim.x + threadIdx.x;
    if (i < n) p[i] = 0;
}

__global__ void count_kernel(const void* __restrict__ ei, int* __restrict__ deg)
{
    int e = blockIdx.x * blockDim.x + threadIdx.x;
    if (e >= N_EDGES) return;
    int d = load_idx(ei, (long long)N_EDGES + e);
    atomicAdd(&deg[d], 1);
}

__global__ void scan_local_kernel(const int* __restrict__ deg,
                                  int* __restrict__ off,
                                  int* __restrict__ bsum)
{
    __shared__ int tmp[256];
    int t = threadIdx.x;
    int node = blockIdx.x * 256 + t;
    int v = (node < N_NODES) ? deg[node] : 0;
    tmp[t] = v;
    __syncthreads();
    #pragma unroll
    for (int o = 1; o < 256; o <<= 1) {
        int u = (t >= o) ? tmp[t - o] : 0;
        __syncthreads();
        tmp[t] += u;
        __syncthreads();
    }
    if (node < N_NODES) off[node] = tmp[t] - v;
    if (t == 255) bsum[blockIdx.x] = tmp[255];
}

__global__ void scan_bsum_kernel(int* __restrict__ bsum, int* __restrict__ off)
{
    __shared__ int tmp[256];
    int t = threadIdx.x;
    int v = (t < SCAN_BLOCKS) ? bsum[t] : 0;
    tmp[t] = v;
    __syncthreads();
    #pragma unroll
    for (int o = 1; o < 256; o <<= 1) {
        int u = (t >= o) ? tmp[t - o] : 0;
        __syncthreads();
        tmp[t] += u;
        __syncthreads();
    }
    if (t < SCAN_BLOCKS) bsum[t] = tmp[t] - v;
    if (t == 255) off[N_NODES] = tmp[255];
}

__global__ void scan_add_kernel(int* __restrict__ off,
                                const int* __restrict__ bsum,
                                int* __restrict__ cur)
{
    int node = blockIdx.x * 256 + threadIdx.x;
    if (node >= N_NODES) return;
    int o = off[node] + bsum[blockIdx.x];
    off[node] = o;
    cur[node] = o;
}

__global__ void scatter_kernel(const void* __restrict__ ei,
                               int* __restrict__ cur,
                               int* __restrict__ srcS)
{
    int e = blockIdx.x * blockDim.x + threadIdx.x;
    if (e >= N_EDGES) return;
    int s = load_idx(ei, e);
    int d = load_idx(ei, (long long)N_EDGES + e);
    int pos = atomicAdd(&cur[d], 1);
    srcS[pos] = s;
}

// ================= aggregation (warp per dst node) =================
__global__ void agg_kernel(const int* __restrict__ off,
                           const int* __restrict__ srcS,
                           const float* __restrict__ scores,
                           const float* __restrict__ h,
                           float* __restrict__ aF,
                           float* __restrict__ aB)
{
    int node = (blockIdx.x * blockDim.x + threadIdx.x) >> 5;
    int lane = threadIdx.x & 31;
    if (node >= N_NODES) return;
    int lo = off[node], hi = off[node + 1];
    float sd = scores[node];
    const float4* h4 = reinterpret_cast<const float4*>(h);
    float4 af = make_float4(0.f, 0.f, 0.f, 0.f);
    float4 ab = make_float4(0.f, 0.f, 0.f, 0.f);
    int e = lo;
    for (; e + 4 <= hi; e += 4) {
        int s0 = srcS[e + 0], s1 = srcS[e + 1], s2 = srcS[e + 2], s3 = srcS[e + 3];
        float c0 = scores[s0], c1 = scores[s1], c2 = scores[s2], c3 = scores[s3];
        float4 v0 = h4[(size_t)s0 * 32 + lane];
        float4 v1 = h4[(size_t)s1 * 32 + lane];
        float4 v2 = h4[(size_t)s2 * 32 + lane];
        float4 v3 = h4[(size_t)s3 * 32 + lane];
        float a0 = 1.0f / (1.0f + __expf(sd - c0));
        float a1 = 1.0f / (1.0f + __expf(sd - c1));
        float a2 = 1.0f / (1.0f + __expf(sd - c2));
        float a3 = 1.0f / (1.0f + __expf(sd - c3));
        af.x += v0.x*a0 + v1.x*a1 + v2.x*a2 + v3.x*a3;
        af.y += v0.y*a0 + v1.y*a1 + v2.y*a2 + v3.y*a3;
        af.z += v0.z*a0 + v1.z*a1 + v2.z*a2 + v3.z*a3;
        af.w += v0.w*a0 + v1.w*a1 + v2.w*a2 + v3.w*a3;
        float b0 = 1.f-a0, b1 = 1.f-a1, b2 = 1.f-a2, b3 = 1.f-a3;
        ab.x += v0.x*b0 + v1.x*b1 + v2.x*b2 + v3.x*b3;
        ab.y += v0.y*b0 + v1.y*b1 + v2.y*b2 + v3.y*b3;
        ab.z += v0.z*b0 + v1.z*b1 + v2.z*b2 + v3.z*b3;
        ab.w += v0.w*b0 + v1.w*b1 + v2.w*b2 + v3.w*b3;
    }
    for (; e < hi; e++) {
        int s = srcS[e];
        float a = 1.0f / (1.0f + __expf(sd - scores[s]));
        float b = 1.0f - a;
        float4 v = h4[(size_t)s * 32 + lane];
        af.x += v.x*a; af.y += v.y*a; af.z += v.z*a; af.w += v.w*a;
        ab.x += v.x*b; ab.y += v.y*b; ab.z += v.z*b; ab.w += v.w*b;
    }
    reinterpret_cast<float4*>(aF + (size_t)node * DIM)[lane] = af;
    reinterpret_cast<float4*>(aB + (size_t)node * DIM)[lane] = ab;
}

// ================= prep kernels =================
__global__ void prep_M_kernel(const float* __restrict__ Wcomb,
                              const float* __restrict__ Wself,
                              const float* __restrict__ Wfwd,
                              const float* __restrict__ Wbwd,
                              float* __restrict__ M)
{
    int b = blockIdx.x;
    int rc = b & 7;
    int m  = (b >> 3) % 3;
    int l  = b / 24;
    const float* src = (m == 0) ? (Wself + l * DIM * DIM)
                   : (m == 1) ? (Wfwd + l * DIM * DIM)
                              : (Wbwd + l * DIM * DIM);
    int j = threadIdx.x;

    __shared__ float wcs[16][DIM];
    #pragma unroll
    for (int i = 0; i < 16; i++) {
        int row = rc * 16 + i;
        wcs[i][j] = Wcomb[l * DIM * 3 * DIM + row * 3 * DIM + m * DIM + j];
    }
    __syncthreads();

    float acc[16];
    #pragma unroll
    for (int i = 0; i < 16; i++) acc[i] = 0.0f;
    for (int k = 0; k < DIM; k++) {
        float w = src[k * DIM + j];
        #pragma unroll
        for (int i = 0; i < 16; i++) acc[i] += wcs[i][k] * w;
    }
    float* dst = M + (l * 3 + m) * DIM * DIM;
    #pragma unroll
    for (int i = 0; i < 16; i++) dst[(rc * 16 + i) * DIM + j] = acc[i];
}

__global__ void prep_b_kernel(const float* __restrict__ Wcomb,
                              const float* __restrict__ bself,
                              const float* __restrict__ bcomb,
                              float* __restrict__ bc)
{
    int l = blockIdx.x;
    int i = threadIdx.x;
    float s = bcomb[l * DIM + i];
    for (int k = 0; k < DIM; k++)
        s += Wcomb[l * DIM * 3 * DIM + i * 3 * DIM + k] * bself[l * DIM + k];
    bc[l * DIM + i] = s;
}

__global__ void prep_Wbf_kernel(const float* __restrict__ Wemb,
                                const float* __restrict__ M,
                                __nv_bfloat16* __restrict__ Wh,
                                __nv_bfloat16* __restrict__ Wl)
{
    int idx = blockIdx.x * blockDim.x + threadIdx.x;
    if (idx >= 10 * DIM * DIM) return;
    int mat = idx / (DIM * DIM);
    int rem = idx % (DIM * DIM);
    float w = (mat == 0) ? Wemb[rem] : M[(mat - 1) * DIM * DIM + rem];
    __nv_bfloat16 hi = __float2bfloat16_rn(w);
    float lo = w - __bfloat162float(hi);
    Wh[idx] = hi;
    Wl[idx] = __float2bfloat16_rn(lo);
}

// ================= tensor-core GEMM (mma.sync) + fused epilogue =================
#define OFF_BIAS  0
#define OFF_GAMMA 512
#define OFF_BETA  1024
#define OFF_WSC   1536
#define OFF_MU    2048
#define OFF_RS    2560
#define OFF_SC    3072
#define AHI_OFF   4096
#define ALO_OFF   (4096 + 18432)
#define WHI_OFF   (4096 + 36864)
#define WLO_OFF   (4096 + 55296)
#define MM_SMEM   (4096 + 73728)
#define BF_STRIDE 144

__global__ void __launch_bounds__(256, 2)
mm_mma_kernel(const float* __restrict__ A0, const float* __restrict__ A1,
              const float* __restrict__ A2,
              const __nv_bfloat16* __restrict__ Whb,
              const __nv_bfloat16* __restrict__ Wlb,
              const float* __restrict__ bias,
              const float* __restrict__ gamma,
              const float* __restrict__ beta,
              const float* __restrict__ wsc,
              const float* __restrict__ bscp,
              float* __restrict__ hOut,
              float* __restrict__ scoresOut,
              int n, int nsrc, int mode)
{
    extern __shared__ char smem[];
    uint32_t smemU = smem_to_u32(smem);
    int tid = threadIdx.x;
    int lane = tid & 31;
    int warp = tid >> 5;
    int base = blockIdx.x * 128;

    float* bias_s  = (float*)(smem + OFF_BIAS);
    float* gamma_s = (float*)(smem + OFF_GAMMA);
    float* beta_s  = (float*)(smem + OFF_BETA);
    float* wsc_s   = (float*)(smem + OFF_WSC);
    float* mu_s    = (float*)(smem + OFF_MU);
    float* rs_s    = (float*)(smem + OFF_RS);
    float* sc_s    = (float*)(smem + OFF_SC);

    if (tid < 128) {
        bias_s[tid] = bias ? bias[tid] : 0.0f;
        if (mode == 1) { gamma_s[tid] = gamma[tid]; beta_s[tid] = beta[tid]; }
        if (wsc) wsc_s[tid] = wsc[tid];
        sc_s[tid] = 0.0f;
    }

    int mO = (warp >> 2) * 64;
    int nO = (warp & 3) * 32;
    uint32_t aLaneOff = (uint32_t)((lane & 15) * BF_STRIDE + ((lane >> 4) << 4));
    uint32_t bLaneOff = (uint32_t)((lane & 7) * BF_STRIDE + (((lane >> 3) & 1) << 4));

    float acc[4][4][4];
    #pragma unroll
    for (int mt = 0; mt < 4; mt++)
        #pragma unroll
        for (int nt = 0; nt < 4; nt++)
            #pragma unroll
            for (int r = 0; r < 4; r++) acc[mt][nt][r] = 0.0f;

    const int nchunks = nsrc * 2;
    for (int c = 0; c < nchunks; c++) {
        int s = c >> 1;
        int half = c & 1;
        const float* A = (s == 0) ? A0 : (s == 1) ? A1 : A2;

        __syncthreads();   // tiles free (prev chunk's ldmatrix done)

        // --- W chunk via cp.async (16B, 8 per thread), overlapped with A convert
        {
            const char* WhG = (const char*)(Whb + (size_t)s * DIM * DIM);
            const char* WlG = (const char*)(Wlb + (size_t)s * DIM * DIM);
            #pragma unroll
            for (int i = 0; i < 8; i++) {
                int idx = tid + i * 256;       // 0..2047
                int row = idx >> 4;            // 0..127
                int q   = idx & 15;            // 16B chunk in 256B row -> but chunk=128B half
                // 8 chunks of 16B per 128B half-row: q in 0..7 handled by two idx groups
                int qq  = q & 7;
                int which = q >> 3;            // 0 = WHI, 1 = WLO
                uint32_t dst = smemU + (which ? WLO_OFF : WHI_OFF) + row * BF_STRIDE + qq * 16;
                const char* srcp = (which ? WlG : WhG) + row * 256 + half * 128 + qq * 16;
                CP_ASYNC16(dst, srcp);
            }
            CP_ASYNC_COMMIT();
        }

        // --- convert A chunk: 128 rows x 64 k, fp32 -> bf16 hi/lo (packed cvt)
        #pragma unroll
        for (int i = 0; i < 8; i++) {
            int idx = tid + i * 256;
            int row = idx >> 4;
            int k4  = idx & 15;
            int gn = base + row;
            float4 v = make_float4(0.f, 0.f, 0.f, 0.f);
            if (gn < n)
                v = *reinterpret_cast<const float4*>(A + (size_t)gn * DIM + half * 64 + k4 * 4);
            unsigned hi01 = cvt_bf16x2(v.y, v.x);
            unsigned hi23 = cvt_bf16x2(v.w, v.z);
            float hx = __uint_as_float(hi01 << 16);
            float hy = __uint_as_float(hi01 & 0xFFFF0000u);
            float hz = __uint_as_float(hi23 << 16);
            float hw = __uint_as_float(hi23 & 0xFFFF0000u);
            unsigned lo01 = cvt_bf16x2(v.y - hy, v.x - hx);
            unsigned lo23 = cvt_bf16x2(v.w - hw, v.z - hz);
            unsigned off = row * BF_STRIDE + k4 * 8;
            *(unsigned*)(smem + AHI_OFF + off)     = hi01;
            *(unsigned*)(smem + AHI_OFF + off + 4) = hi23;
            *(unsigned*)(smem + ALO_OFF + off)     = lo01;
            *(unsigned*)(smem + ALO_OFF + off + 4) = lo23;
        }
        CP_ASYNC_WAIT0();
        __syncthreads();

        // --- MMA: 4 k16-steps; b-frags loaded per ks, a-frags per mt (low reg pressure)
        #pragma unroll
        for (int ks = 0; ks < 4; ks++) {
            uint32_t kb2 = ks * 32;
            uint32_t bhi[4][2], blo[4][2];
            #pragma unroll
            for (int nt = 0; nt < 4; nt++) {
                uint32_t addr = smemU + WHI_OFF + (nO + nt * 8) * BF_STRIDE + kb2 + bLaneOff;
                LDSM_X2(bhi[nt], addr);
                LDSM_X2(blo[nt], addr + (WLO_OFF - WHI_OFF));
            }
            #pragma unroll
            for (int mt = 0; mt < 4; mt++) {
                uint32_t ahi[4], alo[4];
                uint32_t addr = smemU + AHI_OFF + (mO + mt * 16) * BF_STRIDE + kb2 + aLaneOff;
                LDSM_X4(ahi, addr);
                LDSM_X4(alo, addr + (ALO_OFF - AHI_OFF));
                #pragma unroll
                for (int nt = 0; nt < 4; nt++) {
                    MMA16816(acc[mt][nt], ahi, bhi[nt]);
                    MMA16816(acc[mt][nt], ahi, blo[nt]);
                    MMA16816(acc[mt][nt], alo, bhi[nt]);
                }
            }
        }
    }
    __syncthreads();

    // ---------------- epilogue ----------------
    float* acc_sm = (float*)(smem + AHI_OFF);   // 128 x 129 fp32
    #pragma unroll
    for (int mt = 0; mt < 4; mt++)
        #pragma unroll
        for (int nt = 0; nt < 4; nt++) {
            int R = mO + mt * 16 + (lane >> 2);
            int C = nO + nt * 8 + 2 * (lane & 3);
            acc_sm[R * 129 + C]           = acc[mt][nt][0];
            acc_sm[R * 129 + C + 1]       = acc[mt][nt][1];
            acc_sm[(R + 8) * 129 + C]     = acc[mt][nt][2];
            acc_sm[(R + 8) * 129 + C + 1] = acc[mt][nt][3];
        }
    __syncthreads();

    if (mode == 1 && tid < 128) {
        int r = tid;
        float sum = 0.0f, sq = 0.0f;
        #pragma unroll 4
        for (int j = 0; j < 128; j++) {
            float v = acc_sm[r * 129 + j] + bias_s[j];
            sum += v;
            sq  += v * v;
        }
        float mu = sum * (1.0f / 128.0f);
        mu_s[r] = mu;
        rs_s[r] = rsqrtf(fmaxf(sq * (1.0f / 128.0f) - mu * mu, 0.0f) + LN_EPS);
    }
    __syncthreads();

    #pragma unroll 2
    for (int i = 0; i < 64; i++) {
        int idx = i * 256 + tid;
        int r = idx >> 7;
        int j = idx & 127;
        int gn = base + r;
        float v = acc_sm[r * 129 + j] + bias_s[j];
        float rnew;
        if (mode == 1) {
            float dn = (v - mu_s[r]) * rs_s[r];
            float idv = (gn < n) ? hOut[(size_t)gn * DIM + j] : 0.0f;
            rnew = fmaxf(dn * gamma_s[j] + beta_s[j], 0.0f) + idv;
        } else {
            rnew = fmaxf(v, 0.0f);
        }
        if (gn < n) hOut[(size_t)gn * DIM + j] = rnew;
        if (wsc) {
            float p = rnew * wsc_s[j];
            #pragma unroll
            for (int o = 16; o > 0; o >>= 1) p += __shfl_xor_sync(0xFFFFFFFFu, p, o);
            if (lane == 0) atomicAdd(&sc_s[r], p);
        }
    }
    if (wsc) {
        __syncthreads();
        if (tid < 128 && base + tid < n)
            scoresOut[base + tid] = sc_s[tid] + bscp[0];
    }
}

// ================= pool =================
__device__ __forceinline__ int lb_idx(const void* buf, int n, int val)
{
    int lo = 0, hi = n;
    while (lo < hi) {
        int mid = (lo + hi) >> 1;
        int bv;
        if (g_is64) bv = (int)((const long long*)buf)[mid];
        else        bv = ((const int*)buf)[mid];
        if (bv < val) lo = mid + 1; else hi = mid;
    }
    return lo;
}

__global__ void zero_out_kernel(float* __restrict__ p, int n)
{
    int i = blockIdx.x * blockDim.x + threadIdx.x;
    if (i < n) p[i] = 0.0f;
}

__global__ void pool_kernel(const float* __restrict__ h,
                            const void* __restrict__ batch,
                            float* __restrict__ out)
{
    int g = blockIdx.x;
    int slice = blockIdx.y;
    int j = threadIdx.x;
    __shared__ int s_lo, s_hi;
    if (j == 0) {
        s_lo = lb_idx(batch, N_NODES, g);
        s_hi = lb_idx(batch, N_NODES, g + 1);
    }
    __syncthreads();
    float sum = 0.0f;
    for (int nd = s_lo + slice; nd < s_hi; nd += 8)
        sum += h[(size_t)nd * DIM + j];
    float c = fmaxf((float)(s_hi - s_lo), 1.0f);
    atomicAdd(&out[g * DIM + j], sum / c);
}

// ================= launch =================
extern "C" void kernel_launch(void* const* d_in, const int* in_sizes, int n_in,
                              void* d_out, int out_size)
{
    const float* x      = (const float*)d_in[0];
    const void*  ei     = d_in[1];
    const void*  batch  = d_in[2];
    const float* Wemb   = (const float*)d_in[3];
    const float* bemb   = (const float*)d_in[4];
    const float* Wscore = (const float*)d_in[5];
    const float* bscore = (const float*)d_in[6];
    const float* Wfwd   = (const float*)d_in[7];
    const float* Wbwd   = (const float*)d_in[8];
    const float* Wself  = (const float*)d_in[9];
    const float* bself  = (const float*)d_in[10];
    const float* Wcomb  = (const float*)d_in[11];
    const float* bcomb  = (const float*)d_in[12];
    const float* gamma  = (const float*)d_in[13];
    const float* beta   = (const float*)d_in[14];
    float* out = (float*)d_out;

    float *pH, *pAF, *pAB, *pS, *pM, *pBC;
    __nv_bfloat16 *pWh, *pWl;
    int *pDeg, *pOff, *pCur, *pSrcS, *pBsum;
    cudaGetSymbolAddress((void**)&pH,  g_h);
    cudaGetSymbolAddress((void**)&pAF, g_aF);
    cudaGetSymbolAddress((void**)&pAB, g_aB);
    cudaGetSymbolAddress((void**)&pS,  g_scores);
    cudaGetSymbolAddress((void**)&pM,  g_M);
    cudaGetSymbolAddress((void**)&pBC, g_bc);
    cudaGetSymbolAddress((void**)&pWh, g_Wh);
    cudaGetSymbolAddress((void**)&pWl, g_Wl);
    cudaGetSymbolAddress((void**)&pDeg,  g_deg);
    cudaGetSymbolAddress((void**)&pOff,  g_off);
    cudaGetSymbolAddress((void**)&pCur,  g_cur);
    cudaGetSymbolAddress((void**)&pSrcS, g_srcS);
    cudaGetSymbolAddress((void**)&pBsum, g_bsum);

    cudaFuncSetAttribute(mm_mma_kernel, cudaFuncAttributeMaxDynamicSharedMemorySize, MM_SMEM);

    const int tileBlocks = (N_NODES + 127) / 128;
    const int warpBlocks = (N_NODES + 7) / 8;
    const int edgeThBlocks = (N_EDGES + 255) / 256;

    detect_kernel<<<1, 256>>>((const unsigned int*)ei);

    // CSR build
    zero_int_kernel<<<(N_NODES + 255) / 256, 256>>>(pDeg, N_NODES);
    count_kernel<<<edgeThBlocks, 256>>>(ei, pDeg);
    scan_local_kernel<<<SCAN_BLOCKS, 256>>>(pDeg, pOff, pBsum);
    scan_bsum_kernel<<<1, 256>>>(pBsum, pOff);
    scan_add_kernel<<<SCAN_BLOCKS, 256>>>(pOff, pBsum, pCur);
    scatter_kernel<<<edgeThBlocks, 256>>>(ei, pCur, pSrcS);

    // weight prep
    prep_M_kernel<<<72, 128>>>(Wcomb, Wself, Wfwd, Wbwd, pM);
    prep_b_kernel<<<N_LAYERS, 128>>>(Wcomb, bself, bcomb, pBC);
    prep_Wbf_kernel<<<(10 * DIM * DIM + 255) / 256, 256>>>(Wemb, pM, pWh, pWl);

    // embed: h = relu(x @ Wemb^T + bemb), fused layer-0 scores
    mm_mma_kernel<<<tileBlocks, 256, MM_SMEM>>>(
        x, nullptr, nullptr, pWh, pWl, bemb,
        nullptr, nullptr, Wscore, bscore,
        pH, pS, N_NODES, 1, 0);

    for (int l = 0; l < N_LAYERS; l++) {
        agg_kernel<<<warpBlocks, 256>>>(pOff, pSrcS, pS, pH, pAF, pAB);
        const float* wsc_next = (l + 1 < N_LAYERS) ? (Wscore + (l + 1) * DIM) : nullptr;
        const float* bsc_next = (l + 1 < N_LAYERS) ? (bscore + (l + 1)) : nullptr;
        mm_mma_kernel<<<tileBlocks, 256, MM_SMEM>>>(
            pH, pAF, pAB,
            pWh + (size_t)(1 + l * 3) * DIM * DIM,
            pWl + (size_t)(1 + l * 3) * DIM * DIM,
            pBC + l * DIM, gamma + l * DIM, beta + l * DIM,
            wsc_next, bsc_next,
            pH, pS, N_NODES, 3, 1);
    }

    zero_out_kernel<<<(N_GRAPHS * DIM + 255) / 256, 256>>>(out, N_GRAPHS * DIM);
    pool_kernel<<<dim3(N_GRAPHS, 8), DIM>>>(pH, batch, out);
}